// round 1
// baseline (speedup 1.0000x reference)
#include <cuda_runtime.h>

#define H 128
#define VMAX 50000
#define NDOCS_MAX 20000
#define TILE_ROWS 32
#define GEMM_THREADS 256
#define GEMM_SMEM (128*128*4 + TILE_ROWS*128*4)   // Wt (64KB) + in tile (16KB)

// Scratch (device globals: no allocation allowed)
__device__ float g_H1[VMAX * H];
__device__ float g_H2[VMAX * H];
__device__ float g_doc[NDOCS_MAX * H];

// ---------------------------------------------------------------------------
__global__ void zero_kernel(float* __restrict__ p, int n4) {
    int i = blockIdx.x * blockDim.x + threadIdx.x;
    if (i < n4) ((float4*)p)[i] = make_float4(0.f, 0.f, 0.f, 0.f);
}

__device__ __forceinline__ void red_add_v4(float* addr, float4 v) {
    asm volatile("red.global.add.v4.f32 [%0], {%1,%2,%3,%4};"
                 :: "l"(addr), "f"(v.x), "f"(v.y), "f"(v.z), "f"(v.w)
                 : "memory");
}

// SpMM: out[row] += val * dense[col], one warp per edge, float4 per lane.
__global__ void spmm_kernel(const int* __restrict__ rows, const int* __restrict__ cols,
                            const float* __restrict__ vals, int nnz,
                            const float* __restrict__ dense, float* __restrict__ out) {
    int w = (blockIdx.x * blockDim.x + threadIdx.x) >> 5;
    if (w >= nnz) return;
    int lane = threadIdx.x & 31;
    int r = __ldg(rows + w);
    int c = __ldg(cols + w);
    float v = __ldg(vals + w);
    float4 d = *(const float4*)(dense + (size_t)c * H + lane * 4);
    d.x *= v; d.y *= v; d.z *= v; d.w *= v;
    red_add_v4(out + (size_t)r * H + lane * 4, d);
}

// ---------------------------------------------------------------------------
// Shared GEMM core: block = 256 threads = 8 warps. Warp ty handles rows
// [ty*4, ty*4+4); lane tx handles cols [tx*4, tx*4+4). Wt[k*128+j] in smem
// (float4 over j is conflict-free), input tile broadcast-read.
struct GemmAcc { float a[4][4]; };

__device__ __forceinline__ void gemm_tile_compute(const float* Wt, const float* insh,
                                                  int tx, int ty, GemmAcc& acc) {
    #pragma unroll
    for (int r = 0; r < 4; r++)
        #pragma unroll
        for (int c = 0; c < 4; c++) acc.a[r][c] = 0.f;
    #pragma unroll 4
    for (int k = 0; k < 128; k++) {
        float4 w = ((const float4*)(Wt + k * 128))[tx];
        #pragma unroll
        for (int r = 0; r < 4; r++) {
            float a = insh[(ty * 4 + r) * 128 + k];
            acc.a[r][0] += a * w.x;
            acc.a[r][1] += a * w.y;
            acc.a[r][2] += a * w.z;
            acc.a[r][3] += a * w.w;
        }
    }
}

__device__ __forceinline__ void load_Wt(const float* __restrict__ W, float* Wt, int t) {
    for (int idx = t; idx < 128 * 128; idx += GEMM_THREADS) {
        int j = idx >> 7, k = idx & 127;
        Wt[k * 128 + j] = W[idx];
    }
}

__device__ __forceinline__ void load_in_tile(const float* __restrict__ in, float* insh,
                                             int row0, int N, int t) {
    for (int idx = t; idx < TILE_ROWS * 32; idx += GEMM_THREADS) {
        int r = idx >> 5, k4 = idx & 31;
        float4 v = make_float4(0.f, 0.f, 0.f, 0.f);
        if (row0 + r < N) v = ((const float4*)(in + (size_t)(row0 + r) * 128))[k4];
        ((float4*)(insh + r * 128))[k4] = v;
    }
}

// out = relu(in @ W^T)
__global__ void gemm_relu_kernel(const float* __restrict__ in, const float* __restrict__ W,
                                 float* __restrict__ out, int N) {
    extern __shared__ float sm[];
    float* Wt = sm;
    float* insh = sm + 128 * 128;
    int t = threadIdx.x, tx = t & 31, ty = t >> 5;
    load_Wt(W, Wt, t);
    __syncthreads();
    int ntiles = (N + TILE_ROWS - 1) / TILE_ROWS;
    for (int tile = blockIdx.x; tile < ntiles; tile += gridDim.x) {
        int row0 = tile * TILE_ROWS;
        load_in_tile(in, insh, row0, N, t);
        __syncthreads();
        GemmAcc acc;
        gemm_tile_compute(Wt, insh, tx, ty, acc);
        #pragma unroll
        for (int r = 0; r < 4; r++) {
            int row = row0 + ty * 4 + r;
            if (row < N) {
                float4 o = make_float4(fmaxf(acc.a[r][0], 0.f), fmaxf(acc.a[r][1], 0.f),
                                       fmaxf(acc.a[r][2], 0.f), fmaxf(acc.a[r][3], 0.f));
                ((float4*)(out + (size_t)row * 128))[tx] = o;
            }
        }
        __syncthreads();
    }
}

// out = layernorm(0.3*emb + 0.7*relu(in @ W^T)) + emb
__global__ void gemm_ln_res_kernel(const float* __restrict__ in, const float* __restrict__ W,
                                   const float* __restrict__ emb,
                                   const float* __restrict__ norm_g,
                                   const float* __restrict__ norm_b,
                                   float* __restrict__ out, int N) {
    extern __shared__ float sm[];
    float* Wt = sm;
    float* insh = sm + 128 * 128;
    int t = threadIdx.x, tx = t & 31, ty = t >> 5;
    float4 gv = ((const float4*)norm_g)[tx];
    float4 bv = ((const float4*)norm_b)[tx];
    load_Wt(W, Wt, t);
    __syncthreads();
    int ntiles = (N + TILE_ROWS - 1) / TILE_ROWS;
    for (int tile = blockIdx.x; tile < ntiles; tile += gridDim.x) {
        int row0 = tile * TILE_ROWS;
        load_in_tile(in, insh, row0, N, t);
        __syncthreads();
        GemmAcc acc;
        gemm_tile_compute(Wt, insh, tx, ty, acc);

        float z[4][4];
        float4 e[4];
        float s[4], q[4];
        #pragma unroll
        for (int r = 0; r < 4; r++) {
            int row = row0 + ty * 4 + r;
            e[r] = make_float4(0.f, 0.f, 0.f, 0.f);
            if (row < N) e[r] = ((const float4*)(emb + (size_t)row * 128))[tx];
            z[r][0] = 0.3f * e[r].x + 0.7f * fmaxf(acc.a[r][0], 0.f);
            z[r][1] = 0.3f * e[r].y + 0.7f * fmaxf(acc.a[r][1], 0.f);
            z[r][2] = 0.3f * e[r].z + 0.7f * fmaxf(acc.a[r][2], 0.f);
            z[r][3] = 0.3f * e[r].w + 0.7f * fmaxf(acc.a[r][3], 0.f);
            s[r] = z[r][0] + z[r][1] + z[r][2] + z[r][3];
            q[r] = z[r][0]*z[r][0] + z[r][1]*z[r][1] + z[r][2]*z[r][2] + z[r][3]*z[r][3];
        }
        #pragma unroll
        for (int off = 16; off > 0; off >>= 1) {
            #pragma unroll
            for (int r = 0; r < 4; r++) {
                s[r] += __shfl_xor_sync(0xffffffffu, s[r], off);
                q[r] += __shfl_xor_sync(0xffffffffu, q[r], off);
            }
        }
        #pragma unroll
        for (int r = 0; r < 4; r++) {
            int row = row0 + ty * 4 + r;
            if (row < N) {
                float mean = s[r] * (1.f / 128.f);
                float var = q[r] * (1.f / 128.f) - mean * mean;
                float inv = rsqrtf(var + 1e-5f);
                float4 o;
                o.x = (z[r][0] - mean) * inv * gv.x + bv.x + e[r].x;
                o.y = (z[r][1] - mean) * inv * gv.y + bv.y + e[r].y;
                o.z = (z[r][2] - mean) * inv * gv.z + bv.z + e[r].z;
                o.w = (z[r][3] - mean) * inv * gv.w + bv.w + e[r].w;
                ((float4*)(out + (size_t)row * 128))[tx] = o;
            }
        }
        __syncthreads();
    }
}

// logits = relu(in @ mlpW^T + mlp_b) @ clfW^T + clf_b
__global__ void head_kernel(const float* __restrict__ in, const float* __restrict__ W,
                            const float* __restrict__ mlp_b,
                            const float* __restrict__ clf_W,
                            const float* __restrict__ clf_b,
                            float* __restrict__ out, int N) {
    extern __shared__ float sm[];
    float* Wt = sm;
    float* insh = sm + 128 * 128;
    int t = threadIdx.x, tx = t & 31, ty = t >> 5;
    float4 mb = ((const float4*)mlp_b)[tx];
    float4 c0 = ((const float4*)clf_W)[tx];
    float4 c1 = ((const float4*)(clf_W + 128))[tx];
    float cb0 = clf_b[0], cb1 = clf_b[1];
    load_Wt(W, Wt, t);
    __syncthreads();
    int ntiles = (N + TILE_ROWS - 1) / TILE_ROWS;
    for (int tile = blockIdx.x; tile < ntiles; tile += gridDim.x) {
        int row0 = tile * TILE_ROWS;
        load_in_tile(in, insh, row0, N, t);
        __syncthreads();
        GemmAcc acc;
        gemm_tile_compute(Wt, insh, tx, ty, acc);

        float p0[4], p1[4];
        #pragma unroll
        for (int r = 0; r < 4; r++) {
            float h0 = fmaxf(acc.a[r][0] + mb.x, 0.f);
            float h1 = fmaxf(acc.a[r][1] + mb.y, 0.f);
            float h2 = fmaxf(acc.a[r][2] + mb.z, 0.f);
            float h3 = fmaxf(acc.a[r][3] + mb.w, 0.f);
            p0[r] = h0 * c0.x + h1 * c0.y + h2 * c0.z + h3 * c0.w;
            p1[r] = h0 * c1.x + h1 * c1.y + h2 * c1.z + h3 * c1.w;
        }
        #pragma unroll
        for (int off = 16; off > 0; off >>= 1) {
            #pragma unroll
            for (int r = 0; r < 4; r++) {
                p0[r] += __shfl_xor_sync(0xffffffffu, p0[r], off);
                p1[r] += __shfl_xor_sync(0xffffffffu, p1[r], off);
            }
        }
        if (tx == 0) {
            #pragma unroll
            for (int r = 0; r < 4; r++) {
                int row = row0 + ty * 4 + r;
                if (row < N) {
                    out[(size_t)row * 2 + 0] = p0[r] + cb0;
                    out[(size_t)row * 2 + 1] = p1[r] + cb1;
                }
            }
        }
        __syncthreads();
    }
}

// ---------------------------------------------------------------------------
extern "C" void kernel_launch(void* const* d_in, const int* in_sizes, int n_in,
                              void* d_out, int out_size) {
    const int*   A_row  = (const int*)d_in[0];
    const int*   A_col  = (const int*)d_in[1];
    const float* A_val  = (const float*)d_in[2];
    const int*   X_row  = (const int*)d_in[3];
    const int*   X_col  = (const int*)d_in[4];
    const float* X_val  = (const float*)d_in[5];
    const float* emb_W  = (const float*)d_in[6];
    const float* lin1_W = (const float*)d_in[7];
    const float* lin2_W = (const float*)d_in[8];
    const float* norm_g = (const float*)d_in[9];
    const float* norm_b = (const float*)d_in[10];
    const float* mlp_W  = (const float*)d_in[11];
    const float* mlp_b  = (const float*)d_in[12];
    const float* clf_W  = (const float*)d_in[13];
    const float* clf_b  = (const float*)d_in[14];
    float* out = (float*)d_out;

    int E     = in_sizes[0];
    int NNZ   = in_sizes[3];
    int V     = in_sizes[6] / H;
    int NDOCS = out_size / 2;

    cudaFuncSetAttribute(gemm_relu_kernel,   cudaFuncAttributeMaxDynamicSharedMemorySize, GEMM_SMEM);
    cudaFuncSetAttribute(gemm_ln_res_kernel, cudaFuncAttributeMaxDynamicSharedMemorySize, GEMM_SMEM);
    cudaFuncSetAttribute(head_kernel,        cudaFuncAttributeMaxDynamicSharedMemorySize, GEMM_SMEM);

    float *h1, *h2, *dc;
    cudaGetSymbolAddress((void**)&h1, g_H1);
    cudaGetSymbolAddress((void**)&h2, g_H2);
    cudaGetSymbolAddress((void**)&dc, g_doc);

    const int GEMM_GRID = 296;  // 2 blocks/SM x 148
    int vh4  = V * H / 4;
    int dh4  = NDOCS * H / 4;
    int spmmA_blocks = (E + 7) / 8;     // 8 warps/block, warp per edge
    int spmmX_blocks = (NNZ + 7) / 8;

    // 1) H1 = A @ emb
    zero_kernel<<<(vh4 + 255) / 256, 256>>>(h1, vh4);
    spmm_kernel<<<spmmA_blocks, 256>>>(A_row, A_col, A_val, E, emb_W, h1);
    // 2) H2 = relu(H1 @ lin1^T)
    gemm_relu_kernel<<<GEMM_GRID, GEMM_THREADS, GEMM_SMEM>>>(h1, lin1_W, h2, V);
    // 3) H1 = A @ H2
    zero_kernel<<<(vh4 + 255) / 256, 256>>>(h1, vh4);
    spmm_kernel<<<spmmA_blocks, 256>>>(A_row, A_col, A_val, E, h2, h1);
    // 4) H2 = layernorm(0.3*emb + 0.7*relu(H1 @ lin2^T)) + emb
    gemm_ln_res_kernel<<<GEMM_GRID, GEMM_THREADS, GEMM_SMEM>>>(h1, lin2_W, emb_W,
                                                              norm_g, norm_b, h2, V);
    // 5) doc = X @ H2   (== X@word_H + X@emb since H2 carries +emb)
    zero_kernel<<<(dh4 + 255) / 256, 256>>>(dc, dh4);
    spmm_kernel<<<spmmX_blocks, 256>>>(X_row, X_col, X_val, NNZ, h2, dc);
    // 6) logits = relu(doc @ mlp^T + b) @ clf^T + clf_b
    head_kernel<<<GEMM_GRID, GEMM_THREADS, GEMM_SMEM>>>(dc, mlp_W, mlp_b, clf_W, clf_b,
                                                        out, NDOCS);
}

// round 2
// speedup vs baseline: 1.3920x; 1.3920x over previous
#include <cuda_runtime.h>

#define H 128
#define VMAX 50000
#define NDOCS_MAX 20000
#define EMAX 1600000
#define TILE_ROWS 32
#define GEMM_THREADS 256
#define GEMM_SMEM (128*128*4 + TILE_ROWS*128*4)   // Wt (64KB) + in tile (16KB)

// Scratch (device globals: no allocation allowed)
__device__ float g_H1[VMAX * H];
__device__ float g_H2[VMAX * H];
__device__ float g_doc[NDOCS_MAX * H];
__device__ int2  g_edges[EMAX];        // packed (col, val-bits), CSR order
__device__ int   g_cnt[VMAX + 1];
__device__ int   g_ptr[VMAX + 1];
__device__ int   g_cur[VMAX + 1];

// ---------------------------------------------------------------------------
// CSR build: zero counts -> histogram -> exclusive scan -> atomic scatter
// ---------------------------------------------------------------------------
__global__ void zero_int_kernel(int* __restrict__ p, int n) {
    int i = blockIdx.x * blockDim.x + threadIdx.x;
    if (i < n) p[i] = 0;
}

__global__ void hist_kernel(const int* __restrict__ rows, int nnz, int* __restrict__ cnt) {
    int e = blockIdx.x * blockDim.x + threadIdx.x;
    if (e < nnz) atomicAdd(&cnt[__ldg(rows + e)], 1);
}

// Single-block chunked exclusive scan over n entries (n ~ 50001).
// Writes exclusive prefix into ptr AND a working copy into cur.
__global__ void scan_kernel(const int* __restrict__ cnt, int* __restrict__ ptr,
                            int* __restrict__ cur, int n) {
    __shared__ int sm[1024];
    __shared__ int carry;
    if (threadIdx.x == 0) carry = 0;
    __syncthreads();
    for (int base = 0; base < n; base += 1024) {
        int i = base + threadIdx.x;
        int v = (i < n) ? cnt[i] : 0;
        sm[threadIdx.x] = v;
        __syncthreads();
        #pragma unroll
        for (int off = 1; off < 1024; off <<= 1) {
            int add = (threadIdx.x >= off) ? sm[threadIdx.x - off] : 0;
            __syncthreads();
            sm[threadIdx.x] += add;
            __syncthreads();
        }
        int excl = carry + sm[threadIdx.x] - v;
        if (i < n) { ptr[i] = excl; cur[i] = excl; }
        __syncthreads();
        if (threadIdx.x == 1023) carry += sm[1023];
        __syncthreads();
    }
}

__global__ void scatter_kernel(const int* __restrict__ rows, const int* __restrict__ cols,
                               const float* __restrict__ vals, int nnz,
                               int* __restrict__ cur, int2* __restrict__ edges) {
    int e = blockIdx.x * blockDim.x + threadIdx.x;
    if (e < nnz) {
        int r = __ldg(rows + e);
        int p = atomicAdd(&cur[r], 1);
        edges[p] = make_int2(__ldg(cols + e), __float_as_int(__ldg(vals + e)));
    }
}

// ---------------------------------------------------------------------------
// CSR SpMM: warp per output row, register float4 accumulator, single store.
// ---------------------------------------------------------------------------
__global__ void spmm_csr_kernel(const int* __restrict__ ptr, const int2* __restrict__ edges,
                                const float* __restrict__ dense, float* __restrict__ out,
                                int nrows) {
    int r = (blockIdx.x * blockDim.x + threadIdx.x) >> 5;
    if (r >= nrows) return;
    int lane = threadIdx.x & 31;
    int s = __ldg(ptr + r);
    int e = __ldg(ptr + r + 1);
    float4 acc = make_float4(0.f, 0.f, 0.f, 0.f);
    int i = s;
    for (; i + 4 <= e; i += 4) {
        int2 m0 = __ldg(edges + i);
        int2 m1 = __ldg(edges + i + 1);
        int2 m2 = __ldg(edges + i + 2);
        int2 m3 = __ldg(edges + i + 3);
        float4 d0 = __ldg((const float4*)(dense + (size_t)m0.x * H) + lane);
        float4 d1 = __ldg((const float4*)(dense + (size_t)m1.x * H) + lane);
        float4 d2 = __ldg((const float4*)(dense + (size_t)m2.x * H) + lane);
        float4 d3 = __ldg((const float4*)(dense + (size_t)m3.x * H) + lane);
        float v0 = __int_as_float(m0.y), v1 = __int_as_float(m1.y);
        float v2 = __int_as_float(m2.y), v3 = __int_as_float(m3.y);
        acc.x += v0 * d0.x; acc.y += v0 * d0.y; acc.z += v0 * d0.z; acc.w += v0 * d0.w;
        acc.x += v1 * d1.x; acc.y += v1 * d1.y; acc.z += v1 * d1.z; acc.w += v1 * d1.w;
        acc.x += v2 * d2.x; acc.y += v2 * d2.y; acc.z += v2 * d2.z; acc.w += v2 * d2.w;
        acc.x += v3 * d3.x; acc.y += v3 * d3.y; acc.z += v3 * d3.z; acc.w += v3 * d3.w;
    }
    for (; i < e; i++) {
        int2 m = __ldg(edges + i);
        float v = __int_as_float(m.y);
        float4 d = __ldg((const float4*)(dense + (size_t)m.x * H) + lane);
        acc.x += v * d.x; acc.y += v * d.y; acc.z += v * d.z; acc.w += v * d.w;
    }
    ((float4*)(out + (size_t)r * H))[lane] = acc;
}

// ---------------------------------------------------------------------------
// Dense GEMM core (unchanged from R1): block = 256 threads = 8 warps.
// ---------------------------------------------------------------------------
struct GemmAcc { float a[4][4]; };

__device__ __forceinline__ void gemm_tile_compute(const float* Wt, const float* insh,
                                                  int tx, int ty, GemmAcc& acc) {
    #pragma unroll
    for (int r = 0; r < 4; r++)
        #pragma unroll
        for (int c = 0; c < 4; c++) acc.a[r][c] = 0.f;
    #pragma unroll 4
    for (int k = 0; k < 128; k++) {
        float4 w = ((const float4*)(Wt + k * 128))[tx];
        #pragma unroll
        for (int r = 0; r < 4; r++) {
            float a = insh[(ty * 4 + r) * 128 + k];
            acc.a[r][0] += a * w.x;
            acc.a[r][1] += a * w.y;
            acc.a[r][2] += a * w.z;
            acc.a[r][3] += a * w.w;
        }
    }
}

__device__ __forceinline__ void load_Wt(const float* __restrict__ W, float* Wt, int t) {
    for (int idx = t; idx < 128 * 128; idx += GEMM_THREADS) {
        int j = idx >> 7, k = idx & 127;
        Wt[k * 128 + j] = W[idx];
    }
}

__device__ __forceinline__ void load_in_tile(const float* __restrict__ in, float* insh,
                                             int row0, int N, int t) {
    for (int idx = t; idx < TILE_ROWS * 32; idx += GEMM_THREADS) {
        int r = idx >> 5, k4 = idx & 31;
        float4 v = make_float4(0.f, 0.f, 0.f, 0.f);
        if (row0 + r < N) v = ((const float4*)(in + (size_t)(row0 + r) * 128))[k4];
        ((float4*)(insh + r * 128))[k4] = v;
    }
}

// out = relu(in @ W^T)
__global__ void gemm_relu_kernel(const float* __restrict__ in, const float* __restrict__ W,
                                 float* __restrict__ out, int N) {
    extern __shared__ float sm[];
    float* Wt = sm;
    float* insh = sm + 128 * 128;
    int t = threadIdx.x, tx = t & 31, ty = t >> 5;
    load_Wt(W, Wt, t);
    __syncthreads();
    int ntiles = (N + TILE_ROWS - 1) / TILE_ROWS;
    for (int tile = blockIdx.x; tile < ntiles; tile += gridDim.x) {
        int row0 = tile * TILE_ROWS;
        load_in_tile(in, insh, row0, N, t);
        __syncthreads();
        GemmAcc acc;
        gemm_tile_compute(Wt, insh, tx, ty, acc);
        #pragma unroll
        for (int r = 0; r < 4; r++) {
            int row = row0 + ty * 4 + r;
            if (row < N) {
                float4 o = make_float4(fmaxf(acc.a[r][0], 0.f), fmaxf(acc.a[r][1], 0.f),
                                       fmaxf(acc.a[r][2], 0.f), fmaxf(acc.a[r][3], 0.f));
                ((float4*)(out + (size_t)row * 128))[tx] = o;
            }
        }
        __syncthreads();
    }
}

// out = layernorm(0.3*emb + 0.7*relu(in @ W^T)) + emb
__global__ void gemm_ln_res_kernel(const float* __restrict__ in, const float* __restrict__ W,
                                   const float* __restrict__ emb,
                                   const float* __restrict__ norm_g,
                                   const float* __restrict__ norm_b,
                                   float* __restrict__ out, int N) {
    extern __shared__ float sm[];
    float* Wt = sm;
    float* insh = sm + 128 * 128;
    int t = threadIdx.x, tx = t & 31, ty = t >> 5;
    float4 gv = ((const float4*)norm_g)[tx];
    float4 bv = ((const float4*)norm_b)[tx];
    load_Wt(W, Wt, t);
    __syncthreads();
    int ntiles = (N + TILE_ROWS - 1) / TILE_ROWS;
    for (int tile = blockIdx.x; tile < ntiles; tile += gridDim.x) {
        int row0 = tile * TILE_ROWS;
        load_in_tile(in, insh, row0, N, t);
        __syncthreads();
        GemmAcc acc;
        gemm_tile_compute(Wt, insh, tx, ty, acc);

        float z[4][4];
        float4 e[4];
        float s[4], q[4];
        #pragma unroll
        for (int r = 0; r < 4; r++) {
            int row = row0 + ty * 4 + r;
            e[r] = make_float4(0.f, 0.f, 0.f, 0.f);
            if (row < N) e[r] = ((const float4*)(emb + (size_t)row * 128))[tx];
            z[r][0] = 0.3f * e[r].x + 0.7f * fmaxf(acc.a[r][0], 0.f);
            z[r][1] = 0.3f * e[r].y + 0.7f * fmaxf(acc.a[r][1], 0.f);
            z[r][2] = 0.3f * e[r].z + 0.7f * fmaxf(acc.a[r][2], 0.f);
            z[r][3] = 0.3f * e[r].w + 0.7f * fmaxf(acc.a[r][3], 0.f);
            s[r] = z[r][0] + z[r][1] + z[r][2] + z[r][3];
            q[r] = z[r][0]*z[r][0] + z[r][1]*z[r][1] + z[r][2]*z[r][2] + z[r][3]*z[r][3];
        }
        #pragma unroll
        for (int off = 16; off > 0; off >>= 1) {
            #pragma unroll
            for (int r = 0; r < 4; r++) {
                s[r] += __shfl_xor_sync(0xffffffffu, s[r], off);
                q[r] += __shfl_xor_sync(0xffffffffu, q[r], off);
            }
        }
        #pragma unroll
        for (int r = 0; r < 4; r++) {
            int row = row0 + ty * 4 + r;
            if (row < N) {
                float mean = s[r] * (1.f / 128.f);
                float var = q[r] * (1.f / 128.f) - mean * mean;
                float inv = rsqrtf(var + 1e-5f);
                float4 o;
                o.x = (z[r][0] - mean) * inv * gv.x + bv.x + e[r].x;
                o.y = (z[r][1] - mean) * inv * gv.y + bv.y + e[r].y;
                o.z = (z[r][2] - mean) * inv * gv.z + bv.z + e[r].z;
                o.w = (z[r][3] - mean) * inv * gv.w + bv.w + e[r].w;
                ((float4*)(out + (size_t)row * 128))[tx] = o;
            }
        }
        __syncthreads();
    }
}

// logits = relu(in @ mlpW^T + mlp_b) @ clfW^T + clf_b
__global__ void head_kernel(const float* __restrict__ in, const float* __restrict__ W,
                            const float* __restrict__ mlp_b,
                            const float* __restrict__ clf_W,
                            const float* __restrict__ clf_b,
                            float* __restrict__ out, int N) {
    extern __shared__ float sm[];
    float* Wt = sm;
    float* insh = sm + 128 * 128;
    int t = threadIdx.x, tx = t & 31, ty = t >> 5;
    float4 mb = ((const float4*)mlp_b)[tx];
    float4 c0 = ((const float4*)clf_W)[tx];
    float4 c1 = ((const float4*)(clf_W + 128))[tx];
    float cb0 = clf_b[0], cb1 = clf_b[1];
    load_Wt(W, Wt, t);
    __syncthreads();
    int ntiles = (N + TILE_ROWS - 1) / TILE_ROWS;
    for (int tile = blockIdx.x; tile < ntiles; tile += gridDim.x) {
        int row0 = tile * TILE_ROWS;
        load_in_tile(in, insh, row0, N, t);
        __syncthreads();
        GemmAcc acc;
        gemm_tile_compute(Wt, insh, tx, ty, acc);

        float p0[4], p1[4];
        #pragma unroll
        for (int r = 0; r < 4; r++) {
            float h0 = fmaxf(acc.a[r][0] + mb.x, 0.f);
            float h1 = fmaxf(acc.a[r][1] + mb.y, 0.f);
            float h2 = fmaxf(acc.a[r][2] + mb.z, 0.f);
            float h3 = fmaxf(acc.a[r][3] + mb.w, 0.f);
            p0[r] = h0 * c0.x + h1 * c0.y + h2 * c0.z + h3 * c0.w;
            p1[r] = h0 * c1.x + h1 * c1.y + h2 * c1.z + h3 * c1.w;
        }
        #pragma unroll
        for (int off = 16; off > 0; off >>= 1) {
            #pragma unroll
            for (int r = 0; r < 4; r++) {
                p0[r] += __shfl_xor_sync(0xffffffffu, p0[r], off);
                p1[r] += __shfl_xor_sync(0xffffffffu, p1[r], off);
            }
        }
        if (tx == 0) {
            #pragma unroll
            for (int r = 0; r < 4; r++) {
                int row = row0 + ty * 4 + r;
                if (row < N) {
                    out[(size_t)row * 2 + 0] = p0[r] + cb0;
                    out[(size_t)row * 2 + 1] = p1[r] + cb1;
                }
            }
        }
        __syncthreads();
    }
}

// ---------------------------------------------------------------------------
static void build_csr(const int* rows, const int* cols, const float* vals, int nnz,
                      int nrows, int* cnt, int* ptr, int* cur, int2* edges) {
    zero_int_kernel<<<(nrows + 256) / 256, 256>>>(cnt, nrows + 1);
    hist_kernel<<<(nnz + 255) / 256, 256>>>(rows, nnz, cnt);
    scan_kernel<<<1, 1024>>>(cnt, ptr, cur, nrows + 1);
    scatter_kernel<<<(nnz + 255) / 256, 256>>>(rows, cols, vals, nnz, cur, edges);
}

extern "C" void kernel_launch(void* const* d_in, const int* in_sizes, int n_in,
                              void* d_out, int out_size) {
    const int*   A_row  = (const int*)d_in[0];
    const int*   A_col  = (const int*)d_in[1];
    const float* A_val  = (const float*)d_in[2];
    const int*   X_row  = (const int*)d_in[3];
    const int*   X_col  = (const int*)d_in[4];
    const float* X_val  = (const float*)d_in[5];
    const float* emb_W  = (const float*)d_in[6];
    const float* lin1_W = (const float*)d_in[7];
    const float* lin2_W = (const float*)d_in[8];
    const float* norm_g = (const float*)d_in[9];
    const float* norm_b = (const float*)d_in[10];
    const float* mlp_W  = (const float*)d_in[11];
    const float* mlp_b  = (const float*)d_in[12];
    const float* clf_W  = (const float*)d_in[13];
    const float* clf_b  = (const float*)d_in[14];
    float* out = (float*)d_out;

    int E     = in_sizes[0];
    int NNZ   = in_sizes[3];
    int V     = in_sizes[6] / H;
    int NDOCS = out_size / 2;

    cudaFuncSetAttribute(gemm_relu_kernel,   cudaFuncAttributeMaxDynamicSharedMemorySize, GEMM_SMEM);
    cudaFuncSetAttribute(gemm_ln_res_kernel, cudaFuncAttributeMaxDynamicSharedMemorySize, GEMM_SMEM);
    cudaFuncSetAttribute(head_kernel,        cudaFuncAttributeMaxDynamicSharedMemorySize, GEMM_SMEM);

    float *h1, *h2, *dc;
    int *cnt, *ptr, *cur;
    int2 *edges;
    cudaGetSymbolAddress((void**)&h1, g_H1);
    cudaGetSymbolAddress((void**)&h2, g_H2);
    cudaGetSymbolAddress((void**)&dc, g_doc);
    cudaGetSymbolAddress((void**)&cnt, g_cnt);
    cudaGetSymbolAddress((void**)&ptr, g_ptr);
    cudaGetSymbolAddress((void**)&cur, g_cur);
    cudaGetSymbolAddress((void**)&edges, g_edges);

    const int GEMM_GRID = 296;  // 2 blocks/SM x 148
    int spmmA_grid = (V + 7) / 8;       // warp per row, 8 rows/block
    int spmmX_grid = (NDOCS + 7) / 8;

    // CSR(A) — reused for both A-spmms
    build_csr(A_row, A_col, A_val, E, V, cnt, ptr, cur, edges);
    // 1) H1 = A @ emb
    spmm_csr_kernel<<<spmmA_grid, 256>>>(ptr, edges, emb_W, h1, V);
    // 2) H2 = relu(H1 @ lin1^T)
    gemm_relu_kernel<<<GEMM_GRID, GEMM_THREADS, GEMM_SMEM>>>(h1, lin1_W, h2, V);
    // 3) H1 = A @ H2
    spmm_csr_kernel<<<spmmA_grid, 256>>>(ptr, edges, h2, h1, V);
    // 4) H2 = layernorm(0.3*emb + 0.7*relu(H1 @ lin2^T)) + emb
    gemm_ln_res_kernel<<<GEMM_GRID, GEMM_THREADS, GEMM_SMEM>>>(h1, lin2_W, emb_W,
                                                              norm_g, norm_b, h2, V);
    // CSR(X) — reuses the same scratch
    build_csr(X_row, X_col, X_val, NNZ, NDOCS, cnt, ptr, cur, edges);
    // 5) doc = X @ H2   (H2 carries +emb, so this folds both X-spmms)
    spmm_csr_kernel<<<spmmX_grid, 256>>>(ptr, edges, h2, dc, NDOCS);
    // 6) logits = relu(doc @ mlp^T + b) @ clf^T + clf_b
    head_kernel<<<GEMM_GRID, GEMM_THREADS, GEMM_SMEM>>>(dc, mlp_W, mlp_b, clf_W, clf_b,
                                                        out, NDOCS);
}

// round 3
// speedup vs baseline: 1.4025x; 1.0076x over previous
#include <cuda_runtime.h>

#define H 128
#define VMAX 50000
#define EMAX 1600000
#define FUSED_THREADS 256
#define FUSED_SMEM ((128*128 + 8*4*128) * 4)   // Wt 64KB + 8 warps x 4 rows x 128 floats

// Scratch (device globals: no allocation allowed)
__device__ float g_H2[VMAX * H];
__device__ float g_H3[VMAX * H];
__device__ int2  g_edges[EMAX];
__device__ int   g_cnt[VMAX + 1];
__device__ int   g_ptr[VMAX + 1];
__device__ int   g_cur[VMAX + 1];
__device__ int   g_bsum[64];

// ---------------------------------------------------------------------------
// CSR build: zero -> hist(ILP4) -> 3-kernel scan -> scatter(ILP4)
// ---------------------------------------------------------------------------
__global__ void zero_int_kernel(int* __restrict__ p, int n) {
    int i = blockIdx.x * blockDim.x + threadIdx.x;
    if (i < n) p[i] = 0;
}

__global__ void hist_kernel(const int* __restrict__ rows, int nnz, int* __restrict__ cnt) {
    int base = (blockIdx.x * blockDim.x + threadIdx.x) * 4;
    if (base + 4 <= nnz) {
        int4 r4 = *(const int4*)(rows + base);
        atomicAdd(&cnt[r4.x], 1);
        atomicAdd(&cnt[r4.y], 1);
        atomicAdd(&cnt[r4.z], 1);
        atomicAdd(&cnt[r4.w], 1);
    } else {
        for (int e = base; e < nnz; e++) atomicAdd(&cnt[__ldg(rows + e)], 1);
    }
}

// Per-block exclusive scan (1024 elems/block); block totals into bsum.
__global__ void scan_local_kernel(const int* __restrict__ cnt, int* __restrict__ loc,
                                  int* __restrict__ bsum, int n) {
    __shared__ int sm[1024];
    int i = blockIdx.x * 1024 + threadIdx.x;
    int v = (i < n) ? cnt[i] : 0;
    sm[threadIdx.x] = v;
    __syncthreads();
    #pragma unroll
    for (int off = 1; off < 1024; off <<= 1) {
        int add = (threadIdx.x >= off) ? sm[threadIdx.x - off] : 0;
        __syncthreads();
        sm[threadIdx.x] += add;
        __syncthreads();
    }
    if (i < n) loc[i] = sm[threadIdx.x] - v;          // local exclusive
    if (threadIdx.x == 1023) bsum[blockIdx.x] = sm[1023];
}

// Exclusive scan of <=64 block sums, in place.
__global__ void scan_bsum_kernel(int* __restrict__ bsum, int nb) {
    __shared__ int sm[64];
    int t = threadIdx.x;
    int v = (t < nb) ? bsum[t] : 0;
    sm[t] = v;
    __syncthreads();
    #pragma unroll
    for (int off = 1; off < 64; off <<= 1) {
        int add = (t >= off) ? sm[t - off] : 0;
        __syncthreads();
        sm[t] += add;
        __syncthreads();
    }
    if (t < nb) bsum[t] = sm[t] - v;
}

__global__ void scan_add_kernel(int* __restrict__ ptr, int* __restrict__ cur,
                                const int* __restrict__ bsum, int n) {
    int i = blockIdx.x * 1024 + threadIdx.x;
    if (i < n) {
        int v = ptr[i] + bsum[blockIdx.x];
        ptr[i] = v;
        cur[i] = v;
    }
}

__global__ void scatter_kernel(const int* __restrict__ rows, const int* __restrict__ cols,
                               const float* __restrict__ vals, int nnz,
                               int* __restrict__ cur, int2* __restrict__ edges) {
    int base = (blockIdx.x * blockDim.x + threadIdx.x) * 4;
    if (base + 4 <= nnz) {
        int4   r4 = *(const int4*)(rows + base);
        int4   c4 = *(const int4*)(cols + base);
        float4 v4 = *(const float4*)(vals + base);
        int p0 = atomicAdd(&cur[r4.x], 1);
        int p1 = atomicAdd(&cur[r4.y], 1);
        int p2 = atomicAdd(&cur[r4.z], 1);
        int p3 = atomicAdd(&cur[r4.w], 1);
        edges[p0] = make_int2(c4.x, __float_as_int(v4.x));
        edges[p1] = make_int2(c4.y, __float_as_int(v4.y));
        edges[p2] = make_int2(c4.z, __float_as_int(v4.z));
        edges[p3] = make_int2(c4.w, __float_as_int(v4.w));
    } else {
        for (int e = base; e < nnz; e++) {
            int r = __ldg(rows + e);
            int p = atomicAdd(&cur[r], 1);
            edges[p] = make_int2(__ldg(cols + e), __float_as_int(__ldg(vals + e)));
        }
    }
}

// ---------------------------------------------------------------------------
// Fused SpMM + matvec core. Warp owns 4 consecutive rows. Gather into regs,
// stage in per-warp smem row buffer, then register-blocked matvec vs smem Wt.
// Wt layout: Wt[k*128 + j] = W[j*128 + k]; out[j] = sum_k in[k]*W[j,k].
// ---------------------------------------------------------------------------
__device__ __forceinline__ void fma4(float4& o, float a, const float4& w) {
    o.x += a * w.x; o.y += a * w.y; o.z += a * w.z; o.w += a * w.w;
}

__device__ __forceinline__ void load_Wt(const float* __restrict__ W, float* Wt, int t) {
    for (int idx = t; idx < 128 * 128; idx += FUSED_THREADS) {
        int j = idx >> 7, k = idx & 127;
        Wt[k * 128 + j] = W[idx];
    }
}

__device__ __forceinline__ void warp_spmm_matvec(
    const int* __restrict__ ptr, const int2* __restrict__ edges,
    const float* __restrict__ dense, const float* Wt, float* rowbuf,
    int row0, int nrows, int lane, float4 (&out)[4])
{
    float4 acc[4];
    #pragma unroll
    for (int r = 0; r < 4; r++) {
        acc[r] = make_float4(0.f, 0.f, 0.f, 0.f);
        int row = row0 + r;
        if (row < nrows) {
            int s = __ldg(ptr + row);
            int e = __ldg(ptr + row + 1);
            int i = s;
            for (; i + 4 <= e; i += 4) {
                int2 m0 = __ldg(edges + i);
                int2 m1 = __ldg(edges + i + 1);
                int2 m2 = __ldg(edges + i + 2);
                int2 m3 = __ldg(edges + i + 3);
                float4 d0 = __ldg((const float4*)(dense + (size_t)m0.x * H) + lane);
                float4 d1 = __ldg((const float4*)(dense + (size_t)m1.x * H) + lane);
                float4 d2 = __ldg((const float4*)(dense + (size_t)m2.x * H) + lane);
                float4 d3 = __ldg((const float4*)(dense + (size_t)m3.x * H) + lane);
                fma4(acc[r], __int_as_float(m0.y), d0);
                fma4(acc[r], __int_as_float(m1.y), d1);
                fma4(acc[r], __int_as_float(m2.y), d2);
                fma4(acc[r], __int_as_float(m3.y), d3);
            }
            for (; i < e; i++) {
                int2 m = __ldg(edges + i);
                float4 d = __ldg((const float4*)(dense + (size_t)m.x * H) + lane);
                fma4(acc[r], __int_as_float(m.y), d);
            }
        }
    }
    __syncwarp();                         // prev iter's rowbuf reads done
    #pragma unroll
    for (int r = 0; r < 4; r++) ((float4*)rowbuf)[r * 32 + lane] = acc[r];
    __syncwarp();

    #pragma unroll
    for (int r = 0; r < 4; r++) out[r] = make_float4(0.f, 0.f, 0.f, 0.f);
    #pragma unroll 4
    for (int k4 = 0; k4 < 32; k4++) {
        float4 a0 = ((const float4*)rowbuf)[0 * 32 + k4];
        float4 a1 = ((const float4*)rowbuf)[1 * 32 + k4];
        float4 a2 = ((const float4*)rowbuf)[2 * 32 + k4];
        float4 a3 = ((const float4*)rowbuf)[3 * 32 + k4];
        float4 w0 = ((const float4*)Wt)[(k4 * 4 + 0) * 32 + lane];
        float4 w1 = ((const float4*)Wt)[(k4 * 4 + 1) * 32 + lane];
        float4 w2 = ((const float4*)Wt)[(k4 * 4 + 2) * 32 + lane];
        float4 w3 = ((const float4*)Wt)[(k4 * 4 + 3) * 32 + lane];
        fma4(out[0], a0.x, w0); fma4(out[0], a0.y, w1); fma4(out[0], a0.z, w2); fma4(out[0], a0.w, w3);
        fma4(out[1], a1.x, w0); fma4(out[1], a1.y, w1); fma4(out[1], a1.z, w2); fma4(out[1], a1.w, w3);
        fma4(out[2], a2.x, w0); fma4(out[2], a2.y, w1); fma4(out[2], a2.z, w2); fma4(out[2], a2.w, w3);
        fma4(out[3], a3.x, w0); fma4(out[3], a3.y, w1); fma4(out[3], a3.z, w2); fma4(out[3], a3.w, w3);
    }
}

// K1: out = relu(spmm(ptr,edges,dense) @ W^T)
__global__ void fused_spmm_gemm_relu(const int* __restrict__ ptr, const int2* __restrict__ edges,
                                     const float* __restrict__ dense, const float* __restrict__ W,
                                     float* __restrict__ out, int nrows) {
    extern __shared__ float sm[];
    float* Wt = sm;
    int t = threadIdx.x, lane = t & 31, wid = t >> 5;
    float* rowbuf = sm + 128 * 128 + wid * 512;
    load_Wt(W, Wt, t);
    __syncthreads();
    int ntiles = (nrows + 31) / 32;
    for (int tile = blockIdx.x; tile < ntiles; tile += gridDim.x) {
        int row0 = tile * 32 + wid * 4;
        float4 o[4];
        warp_spmm_matvec(ptr, edges, dense, Wt, rowbuf, row0, nrows, lane, o);
        #pragma unroll
        for (int r = 0; r < 4; r++) {
            int row = row0 + r;
            if (row < nrows) {
                float4 v = make_float4(fmaxf(o[r].x, 0.f), fmaxf(o[r].y, 0.f),
                                       fmaxf(o[r].z, 0.f), fmaxf(o[r].w, 0.f));
                ((float4*)(out + (size_t)row * H))[lane] = v;
            }
        }
    }
}

// K2: out = layernorm(0.3*emb + 0.7*relu(spmm @ W^T)) + emb
__global__ void fused_spmm_gemm_ln(const int* __restrict__ ptr, const int2* __restrict__ edges,
                                   const float* __restrict__ dense, const float* __restrict__ W,
                                   const float* __restrict__ emb,
                                   const float* __restrict__ norm_g, const float* __restrict__ norm_b,
                                   float* __restrict__ out, int nrows) {
    extern __shared__ float sm[];
    float* Wt = sm;
    int t = threadIdx.x, lane = t & 31, wid = t >> 5;
    float* rowbuf = sm + 128 * 128 + wid * 512;
    float4 gv = ((const float4*)norm_g)[lane];
    float4 bv = ((const float4*)norm_b)[lane];
    load_Wt(W, Wt, t);
    __syncthreads();
    int ntiles = (nrows + 31) / 32;
    for (int tile = blockIdx.x; tile < ntiles; tile += gridDim.x) {
        int row0 = tile * 32 + wid * 4;
        float4 o[4];
        warp_spmm_matvec(ptr, edges, dense, Wt, rowbuf, row0, nrows, lane, o);

        float4 e[4], z[4];
        float s[4], q[4];
        #pragma unroll
        for (int r = 0; r < 4; r++) {
            int row = row0 + r;
            e[r] = make_float4(0.f, 0.f, 0.f, 0.f);
            if (row < nrows) e[r] = ((const float4*)(emb + (size_t)row * H))[lane];
            z[r].x = 0.3f * e[r].x + 0.7f * fmaxf(o[r].x, 0.f);
            z[r].y = 0.3f * e[r].y + 0.7f * fmaxf(o[r].y, 0.f);
            z[r].z = 0.3f * e[r].z + 0.7f * fmaxf(o[r].z, 0.f);
            z[r].w = 0.3f * e[r].w + 0.7f * fmaxf(o[r].w, 0.f);
            s[r] = z[r].x + z[r].y + z[r].z + z[r].w;
            q[r] = z[r].x*z[r].x + z[r].y*z[r].y + z[r].z*z[r].z + z[r].w*z[r].w;
        }
        #pragma unroll
        for (int off = 16; off > 0; off >>= 1) {
            #pragma unroll
            for (int r = 0; r < 4; r++) {
                s[r] += __shfl_xor_sync(0xffffffffu, s[r], off);
                q[r] += __shfl_xor_sync(0xffffffffu, q[r], off);
            }
        }
        #pragma unroll
        for (int r = 0; r < 4; r++) {
            int row = row0 + r;
            if (row < nrows) {
                float mean = s[r] * (1.f / 128.f);
                float var = q[r] * (1.f / 128.f) - mean * mean;
                float inv = rsqrtf(var + 1e-5f);
                float4 v;
                v.x = (z[r].x - mean) * inv * gv.x + bv.x + e[r].x;
                v.y = (z[r].y - mean) * inv * gv.y + bv.y + e[r].y;
                v.z = (z[r].z - mean) * inv * gv.z + bv.z + e[r].z;
                v.w = (z[r].w - mean) * inv * gv.w + bv.w + e[r].w;
                ((float4*)(out + (size_t)row * H))[lane] = v;
            }
        }
    }
}

// K3: logits = relu(spmm @ mlpW^T + mlp_b) @ clfW^T + clf_b
__global__ void fused_spmm_head(const int* __restrict__ ptr, const int2* __restrict__ edges,
                                const float* __restrict__ dense, const float* __restrict__ W,
                                const float* __restrict__ mlp_b,
                                const float* __restrict__ clf_W, const float* __restrict__ clf_b,
                                float* __restrict__ out, int nrows) {
    extern __shared__ float sm[];
    float* Wt = sm;
    int t = threadIdx.x, lane = t & 31, wid = t >> 5;
    float* rowbuf = sm + 128 * 128 + wid * 512;
    float4 mb = ((const float4*)mlp_b)[lane];
    float4 c0 = ((const float4*)clf_W)[lane];
    float4 c1 = ((const float4*)(clf_W + 128))[lane];
    float cb0 = clf_b[0], cb1 = clf_b[1];
    load_Wt(W, Wt, t);
    __syncthreads();
    int ntiles = (nrows + 31) / 32;
    for (int tile = blockIdx.x; tile < ntiles; tile += gridDim.x) {
        int row0 = tile * 32 + wid * 4;
        float4 o[4];
        warp_spmm_matvec(ptr, edges, dense, Wt, rowbuf, row0, nrows, lane, o);

        float p0[4], p1[4];
        #pragma unroll
        for (int r = 0; r < 4; r++) {
            float h0 = fmaxf(o[r].x + mb.x, 0.f);
            float h1 = fmaxf(o[r].y + mb.y, 0.f);
            float h2 = fmaxf(o[r].z + mb.z, 0.f);
            float h3 = fmaxf(o[r].w + mb.w, 0.f);
            p0[r] = h0 * c0.x + h1 * c0.y + h2 * c0.z + h3 * c0.w;
            p1[r] = h0 * c1.x + h1 * c1.y + h2 * c1.z + h3 * c1.w;
        }
        #pragma unroll
        for (int off = 16; off > 0; off >>= 1) {
            #pragma unroll
            for (int r = 0; r < 4; r++) {
                p0[r] += __shfl_xor_sync(0xffffffffu, p0[r], off);
                p1[r] += __shfl_xor_sync(0xffffffffu, p1[r], off);
            }
        }
        if (lane == 0) {
            #pragma unroll
            for (int r = 0; r < 4; r++) {
                int row = row0 + r;
                if (row < nrows) {
                    out[(size_t)row * 2 + 0] = p0[r] + cb0;
                    out[(size_t)row * 2 + 1] = p1[r] + cb1;
                }
            }
        }
    }
}

// ---------------------------------------------------------------------------
static void build_csr(const int* rows, const int* cols, const float* vals, int nnz,
                      int nrows, int* cnt, int* ptr, int* cur, int* bsum, int2* edges) {
    int n = nrows + 1;
    int sblocks = (n + 1023) / 1024;
    zero_int_kernel<<<(n + 255) / 256, 256>>>(cnt, n);
    hist_kernel<<<(nnz / 4 + 255) / 256, 256>>>(rows, nnz, cnt);
    scan_local_kernel<<<sblocks, 1024>>>(cnt, ptr, bsum, n);
    scan_bsum_kernel<<<1, 64>>>(bsum, sblocks);
    scan_add_kernel<<<sblocks, 1024>>>(ptr, cur, bsum, n);
    scatter_kernel<<<(nnz / 4 + 255) / 256, 256>>>(rows, cols, vals, nnz, cur, edges);
}

extern "C" void kernel_launch(void* const* d_in, const int* in_sizes, int n_in,
                              void* d_out, int out_size) {
    const int*   A_row  = (const int*)d_in[0];
    const int*   A_col  = (const int*)d_in[1];
    const float* A_val  = (const float*)d_in[2];
    const int*   X_row  = (const int*)d_in[3];
    const int*   X_col  = (const int*)d_in[4];
    const float* X_val  = (const float*)d_in[5];
    const float* emb_W  = (const float*)d_in[6];
    const float* lin1_W = (const float*)d_in[7];
    const float* lin2_W = (const float*)d_in[8];
    const float* norm_g = (const float*)d_in[9];
    const float* norm_b = (const float*)d_in[10];
    const float* mlp_W  = (const float*)d_in[11];
    const float* mlp_b  = (const float*)d_in[12];
    const float* clf_W  = (const float*)d_in[13];
    const float* clf_b  = (const float*)d_in[14];
    float* out = (float*)d_out;

    int E     = in_sizes[0];
    int NNZ   = in_sizes[3];
    int V     = in_sizes[6] / H;
    int NDOCS = out_size / 2;

    cudaFuncSetAttribute(fused_spmm_gemm_relu, cudaFuncAttributeMaxDynamicSharedMemorySize, FUSED_SMEM);
    cudaFuncSetAttribute(fused_spmm_gemm_ln,   cudaFuncAttributeMaxDynamicSharedMemorySize, FUSED_SMEM);
    cudaFuncSetAttribute(fused_spmm_head,      cudaFuncAttributeMaxDynamicSharedMemorySize, FUSED_SMEM);

    float *h2, *h3;
    int *cnt, *ptr, *cur, *bsum;
    int2 *edges;
    cudaGetSymbolAddress((void**)&h2, g_H2);
    cudaGetSymbolAddress((void**)&h3, g_H3);
    cudaGetSymbolAddress((void**)&cnt, g_cnt);
    cudaGetSymbolAddress((void**)&ptr, g_ptr);
    cudaGetSymbolAddress((void**)&cur, g_cur);
    cudaGetSymbolAddress((void**)&bsum, g_bsum);
    cudaGetSymbolAddress((void**)&edges, g_edges);

    const int GRID = 296;   // 2 blocks/SM x 148

    // CSR(A) — reused by K1 and K2
    build_csr(A_row, A_col, A_val, E, V, cnt, ptr, cur, bsum, edges);
    // K1: H2 = relu((A @ emb) @ lin1^T)
    fused_spmm_gemm_relu<<<GRID, FUSED_THREADS, FUSED_SMEM>>>(ptr, edges, emb_W, lin1_W, h2, V);
    // K2: H3 = layernorm(0.3*emb + 0.7*relu((A @ H2) @ lin2^T)) + emb
    fused_spmm_gemm_ln<<<GRID, FUSED_THREADS, FUSED_SMEM>>>(ptr, edges, h2, lin2_W, emb_W,
                                                           norm_g, norm_b, h3, V);
    // CSR(X)
    build_csr(X_row, X_col, X_val, NNZ, NDOCS, cnt, ptr, cur, bsum, edges);
    // K3: logits = relu((X @ H3) @ mlp^T + mlp_b) @ clf^T + clf_b
    fused_spmm_head<<<GRID, FUSED_THREADS, FUSED_SMEM>>>(ptr, edges, h3, mlp_W, mlp_b,
                                                        clf_W, clf_b, out, NDOCS);
}

// round 4
// speedup vs baseline: 1.7897x; 1.2761x over previous
#include <cuda_runtime.h>
#include <cuda_fp16.h>

#define H 128
#define VMAX 50000
#define EMAX 1600000
#define TILE_ROWS 32
#define GEMM_THREADS 256
#define GEMM_SMEM (128*128*4 + TILE_ROWS*128*4)   // Wt 64KB + in tile 16KB

// Scratch (device globals: no allocation allowed)
__device__ float  g_F[VMAX * H];        // fp32 spmm outputs / gemm inputs
__device__ __half g_Dh[VMAX * H];       // fp16 dense operand for gathers
__device__ int2   g_edges[EMAX];
__device__ int    g_cnt[VMAX + 1];
__device__ int    g_ptr[VMAX + 1];
__device__ int    g_cur[VMAX + 1];
__device__ int    g_bsum[64];

// ---------------------------------------------------------------------------
// f32x2 packed-FMA helpers (Blackwell FFMA2 — only reachable via PTX)
// ---------------------------------------------------------------------------
#define FMA_F32X2(d, a, b, c) \
    asm("fma.rn.f32x2 %0, %1, %2, %3;" : "=l"(d) : "l"(a), "l"(b), "l"(c))
#define PACK_DUP(out, x) \
    asm("mov.b64 %0, {%1, %1};" : "=l"(out) : "f"(x))
#define UNPACK2(lo, hi, v) \
    asm("mov.b64 {%0, %1}, %2;" : "=f"(lo), "=f"(hi) : "l"(v))

struct U64x2 { unsigned long long a, b; };

// ---------------------------------------------------------------------------
// CSR build: zero -> hist(ILP4) -> scan_local -> scan_add(inline bsum) -> scatter
// ---------------------------------------------------------------------------
__global__ void zero_int_kernel(int* __restrict__ p, int n) {
    int i = blockIdx.x * blockDim.x + threadIdx.x;
    if (i < n) p[i] = 0;
}

__global__ void hist_kernel(const int* __restrict__ rows, int nnz, int* __restrict__ cnt) {
    int base = (blockIdx.x * blockDim.x + threadIdx.x) * 4;
    if (base + 4 <= nnz) {
        int4 r4 = *(const int4*)(rows + base);
        atomicAdd(&cnt[r4.x], 1);
        atomicAdd(&cnt[r4.y], 1);
        atomicAdd(&cnt[r4.z], 1);
        atomicAdd(&cnt[r4.w], 1);
    } else {
        for (int e = base; e < nnz; e++) atomicAdd(&cnt[__ldg(rows + e)], 1);
    }
}

__global__ void scan_local_kernel(const int* __restrict__ cnt, int* __restrict__ loc,
                                  int* __restrict__ bsum, int n) {
    __shared__ int sm[1024];
    int i = blockIdx.x * 1024 + threadIdx.x;
    int v = (i < n) ? cnt[i] : 0;
    sm[threadIdx.x] = v;
    __syncthreads();
    #pragma unroll
    for (int off = 1; off < 1024; off <<= 1) {
        int add = (threadIdx.x >= off) ? sm[threadIdx.x - off] : 0;
        __syncthreads();
        sm[threadIdx.x] += add;
        __syncthreads();
    }
    if (i < n) loc[i] = sm[threadIdx.x] - v;
    if (threadIdx.x == 1023) bsum[blockIdx.x] = sm[1023];
}

// Adds scanned block offsets; scans the (<=64) block sums inline per block.
__global__ void scan_add_kernel(int* __restrict__ ptr, int* __restrict__ cur,
                                const int* __restrict__ bsum, int n, int nb) {
    __shared__ int sb[64];
    int t = threadIdx.x;
    if (t < 64) sb[t] = (t < nb) ? bsum[t] : 0;
    __syncthreads();
    if (t == 0) {
        int run = 0;
        for (int i = 0; i < 64; i++) { int v = sb[i]; sb[i] = run; run += v; }
    }
    __syncthreads();
    int i = blockIdx.x * 1024 + t;
    if (i < n) {
        int v = ptr[i] + sb[blockIdx.x];
        ptr[i] = v;
        cur[i] = v;
    }
}

__global__ void scatter_kernel(const int* __restrict__ rows, const int* __restrict__ cols,
                               const float* __restrict__ vals, int nnz,
                               int* __restrict__ cur, int2* __restrict__ edges) {
    int base = (blockIdx.x * blockDim.x + threadIdx.x) * 4;
    if (base + 4 <= nnz) {
        int4   r4 = *(const int4*)(rows + base);
        int4   c4 = *(const int4*)(cols + base);
        float4 v4 = *(const float4*)(vals + base);
        int p0 = atomicAdd(&cur[r4.x], 1);
        int p1 = atomicAdd(&cur[r4.y], 1);
        int p2 = atomicAdd(&cur[r4.z], 1);
        int p3 = atomicAdd(&cur[r4.w], 1);
        edges[p0] = make_int2(c4.x, __float_as_int(v4.x));
        edges[p1] = make_int2(c4.y, __float_as_int(v4.y));
        edges[p2] = make_int2(c4.z, __float_as_int(v4.z));
        edges[p3] = make_int2(c4.w, __float_as_int(v4.w));
    } else {
        for (int e = base; e < nnz; e++) {
            int r = __ldg(rows + e);
            int p = atomicAdd(&cur[r], 1);
            edges[p] = make_int2(__ldg(cols + e), __float_as_int(__ldg(vals + e)));
        }
    }
}

// ---------------------------------------------------------------------------
// fp32 -> fp16 convert
// ---------------------------------------------------------------------------
__global__ void f2h_kernel(const float* __restrict__ src, __half* __restrict__ dst, int n4) {
    int i = blockIdx.x * blockDim.x + threadIdx.x;
    if (i < n4) {
        float4 v = ((const float4*)src)[i];
        __half2* d = (__half2*)dst;
        d[2 * i]     = __floats2half2_rn(v.x, v.y);
        d[2 * i + 1] = __floats2half2_rn(v.z, v.w);
    }
}

// ---------------------------------------------------------------------------
// CSR SpMM with fp16 dense operand, fp32 accumulate/output. Warp per row.
// ---------------------------------------------------------------------------
__device__ __forceinline__ void acc_h(float4& acc, float v, uint2 d) {
    float2 f0 = __half22float2(*reinterpret_cast<__half2*>(&d.x));
    float2 f1 = __half22float2(*reinterpret_cast<__half2*>(&d.y));
    acc.x += v * f0.x; acc.y += v * f0.y; acc.z += v * f1.x; acc.w += v * f1.y;
}

__global__ void spmm_h_kernel(const int* __restrict__ ptr, const int2* __restrict__ edges,
                              const __half* __restrict__ dense, float* __restrict__ out,
                              int nrows) {
    int r = (blockIdx.x * blockDim.x + threadIdx.x) >> 5;
    if (r >= nrows) return;
    int lane = threadIdx.x & 31;
    int s = __ldg(ptr + r);
    int e = __ldg(ptr + r + 1);
    float4 acc = make_float4(0.f, 0.f, 0.f, 0.f);
    const uint2* db = (const uint2*)dense;
    int i = s;
    for (; i + 4 <= e; i += 4) {
        int2 m0 = __ldg(edges + i);
        int2 m1 = __ldg(edges + i + 1);
        int2 m2 = __ldg(edges + i + 2);
        int2 m3 = __ldg(edges + i + 3);
        uint2 d0 = __ldg(db + (size_t)m0.x * 32 + lane);
        uint2 d1 = __ldg(db + (size_t)m1.x * 32 + lane);
        uint2 d2 = __ldg(db + (size_t)m2.x * 32 + lane);
        uint2 d3 = __ldg(db + (size_t)m3.x * 32 + lane);
        acc_h(acc, __int_as_float(m0.y), d0);
        acc_h(acc, __int_as_float(m1.y), d1);
        acc_h(acc, __int_as_float(m2.y), d2);
        acc_h(acc, __int_as_float(m3.y), d3);
    }
    for (; i < e; i++) {
        int2 m = __ldg(edges + i);
        uint2 d = __ldg(db + (size_t)m.x * 32 + lane);
        acc_h(acc, __int_as_float(m.y), d);
    }
    ((float4*)(out + (size_t)r * H))[lane] = acc;
}

// ---------------------------------------------------------------------------
// Dense GEMM core with f32x2 packed FMA. Block = 256 threads = 8 warps.
// Warp ty: rows [ty*4, ty*4+4); lane tx: cols [tx*4, tx*4+4).
// ---------------------------------------------------------------------------
__device__ __forceinline__ void load_Wt(const float* __restrict__ W, float* Wt, int t) {
    for (int idx = t; idx < 128 * 128; idx += GEMM_THREADS) {
        int j = idx >> 7, k = idx & 127;
        Wt[k * 128 + j] = W[idx];
    }
}

__device__ __forceinline__ void load_in_tile(const float* __restrict__ in, float* insh,
                                             int row0, int N, int t) {
    for (int idx = t; idx < TILE_ROWS * 32; idx += GEMM_THREADS) {
        int r = idx >> 5, k4 = idx & 31;
        float4 v = make_float4(0.f, 0.f, 0.f, 0.f);
        if (row0 + r < N) v = ((const float4*)(in + (size_t)(row0 + r) * 128))[k4];
        ((float4*)(insh + r * 128))[k4] = v;
    }
}

__device__ __forceinline__ void gemm_tile_f2(const float* Wt, const float* insh,
                                             int tx, int ty, float4 (&out)[4]) {
    unsigned long long a01[4], a23[4];
    #pragma unroll
    for (int r = 0; r < 4; r++) { a01[r] = 0ull; a23[r] = 0ull; }
    #pragma unroll 4
    for (int k = 0; k < 128; k++) {
        U64x2 w = ((const U64x2*)(Wt + k * 128))[tx];
        #pragma unroll
        for (int r = 0; r < 4; r++) {
            float av = insh[(ty * 4 + r) * 128 + k];
            unsigned long long aa;
            PACK_DUP(aa, av);
            FMA_F32X2(a01[r], aa, w.a, a01[r]);
            FMA_F32X2(a23[r], aa, w.b, a23[r]);
        }
    }
    #pragma unroll
    for (int r = 0; r < 4; r++) {
        UNPACK2(out[r].x, out[r].y, a01[r]);
        UNPACK2(out[r].z, out[r].w, a23[r]);
    }
}

// K1: outh = fp16(relu(in @ W^T))
__global__ void gemm_relu_h_kernel(const float* __restrict__ in, const float* __restrict__ W,
                                   __half* __restrict__ outh, int N) {
    extern __shared__ float sm[];
    float* Wt = sm;
    float* insh = sm + 128 * 128;
    int t = threadIdx.x, tx = t & 31, ty = t >> 5;
    load_Wt(W, Wt, t);
    __syncthreads();
    int ntiles = (N + TILE_ROWS - 1) / TILE_ROWS;
    for (int tile = blockIdx.x; tile < ntiles; tile += gridDim.x) {
        int row0 = tile * TILE_ROWS;
        load_in_tile(in, insh, row0, N, t);
        __syncthreads();
        float4 o[4];
        gemm_tile_f2(Wt, insh, tx, ty, o);
        #pragma unroll
        for (int r = 0; r < 4; r++) {
            int row = row0 + ty * 4 + r;
            if (row < N) {
                __half2 h0 = __floats2half2_rn(fmaxf(o[r].x, 0.f), fmaxf(o[r].y, 0.f));
                __half2 h1 = __floats2half2_rn(fmaxf(o[r].z, 0.f), fmaxf(o[r].w, 0.f));
                __half2* d = (__half2*)(outh + (size_t)row * H);
                d[tx * 2]     = h0;
                d[tx * 2 + 1] = h1;
            }
        }
        __syncthreads();
    }
}

// K2: outh = fp16( layernorm(0.3*emb + 0.7*relu(in @ W^T)) + emb )
__global__ void gemm_ln_h_kernel(const float* __restrict__ in, const float* __restrict__ W,
                                 const float* __restrict__ emb,
                                 const float* __restrict__ norm_g, const float* __restrict__ norm_b,
                                 __half* __restrict__ outh, int N) {
    extern __shared__ float sm[];
    float* Wt = sm;
    float* insh = sm + 128 * 128;
    int t = threadIdx.x, tx = t & 31, ty = t >> 5;
    float4 gv = ((const float4*)norm_g)[tx];
    float4 bv = ((const float4*)norm_b)[tx];
    load_Wt(W, Wt, t);
    __syncthreads();
    int ntiles = (N + TILE_ROWS - 1) / TILE_ROWS;
    for (int tile = blockIdx.x; tile < ntiles; tile += gridDim.x) {
        int row0 = tile * TILE_ROWS;
        load_in_tile(in, insh, row0, N, t);
        __syncthreads();
        float4 o[4];
        gemm_tile_f2(Wt, insh, tx, ty, o);

        float4 e[4], z[4];
        float s[4], q[4];
        #pragma unroll
        for (int r = 0; r < 4; r++) {
            int row = row0 + ty * 4 + r;
            e[r] = make_float4(0.f, 0.f, 0.f, 0.f);
            if (row < N) e[r] = ((const float4*)(emb + (size_t)row * H))[tx];
            z[r].x = 0.3f * e[r].x + 0.7f * fmaxf(o[r].x, 0.f);
            z[r].y = 0.3f * e[r].y + 0.7f * fmaxf(o[r].y, 0.f);
            z[r].z = 0.3f * e[r].z + 0.7f * fmaxf(o[r].z, 0.f);
            z[r].w = 0.3f * e[r].w + 0.7f * fmaxf(o[r].w, 0.f);
            s[r] = z[r].x + z[r].y + z[r].z + z[r].w;
            q[r] = z[r].x*z[r].x + z[r].y*z[r].y + z[r].z*z[r].z + z[r].w*z[r].w;
        }
        #pragma unroll
        for (int off = 16; off > 0; off >>= 1) {
            #pragma unroll
            for (int r = 0; r < 4; r++) {
                s[r] += __shfl_xor_sync(0xffffffffu, s[r], off);
                q[r] += __shfl_xor_sync(0xffffffffu, q[r], off);
            }
        }
        #pragma unroll
        for (int r = 0; r < 4; r++) {
            int row = row0 + ty * 4 + r;
            if (row < N) {
                float mean = s[r] * (1.f / 128.f);
                float var = q[r] * (1.f / 128.f) - mean * mean;
                float inv = rsqrtf(var + 1e-5f);
                float vx = (z[r].x - mean) * inv * gv.x + bv.x + e[r].x;
                float vy = (z[r].y - mean) * inv * gv.y + bv.y + e[r].y;
                float vz = (z[r].z - mean) * inv * gv.z + bv.z + e[r].z;
                float vw = (z[r].w - mean) * inv * gv.w + bv.w + e[r].w;
                __half2* d = (__half2*)(outh + (size_t)row * H);
                d[tx * 2]     = __floats2half2_rn(vx, vy);
                d[tx * 2 + 1] = __floats2half2_rn(vz, vw);
            }
        }
        __syncthreads();
    }
}

// K3: logits = relu(in @ mlpW^T + mlp_b) @ clfW^T + clf_b
__global__ void head_kernel(const float* __restrict__ in, const float* __restrict__ W,
                            const float* __restrict__ mlp_b,
                            const float* __restrict__ clf_W, const float* __restrict__ clf_b,
                            float* __restrict__ out, int N) {
    extern __shared__ float sm[];
    float* Wt = sm;
    float* insh = sm + 128 * 128;
    int t = threadIdx.x, tx = t & 31, ty = t >> 5;
    float4 mb = ((const float4*)mlp_b)[tx];
    float4 c0 = ((const float4*)clf_W)[tx];
    float4 c1 = ((const float4*)(clf_W + 128))[tx];
    float cb0 = clf_b[0], cb1 = clf_b[1];
    load_Wt(W, Wt, t);
    __syncthreads();
    int ntiles = (N + TILE_ROWS - 1) / TILE_ROWS;
    for (int tile = blockIdx.x; tile < ntiles; tile += gridDim.x) {
        int row0 = tile * TILE_ROWS;
        load_in_tile(in, insh, row0, N, t);
        __syncthreads();
        float4 o[4];
        gemm_tile_f2(Wt, insh, tx, ty, o);

        float p0[4], p1[4];
        #pragma unroll
        for (int r = 0; r < 4; r++) {
            float h0 = fmaxf(o[r].x + mb.x, 0.f);
            float h1 = fmaxf(o[r].y + mb.y, 0.f);
            float h2 = fmaxf(o[r].z + mb.z, 0.f);
            float h3 = fmaxf(o[r].w + mb.w, 0.f);
            p0[r] = h0 * c0.x + h1 * c0.y + h2 * c0.z + h3 * c0.w;
            p1[r] = h0 * c1.x + h1 * c1.y + h2 * c1.z + h3 * c1.w;
        }
        #pragma unroll
        for (int off = 16; off > 0; off >>= 1) {
            #pragma unroll
            for (int r = 0; r < 4; r++) {
                p0[r] += __shfl_xor_sync(0xffffffffu, p0[r], off);
                p1[r] += __shfl_xor_sync(0xffffffffu, p1[r], off);
            }
        }
        if (tx == 0) {
            #pragma unroll
            for (int r = 0; r < 4; r++) {
                int row = row0 + ty * 4 + r;
                if (row < N) {
                    out[(size_t)row * 2 + 0] = p0[r] + cb0;
                    out[(size_t)row * 2 + 1] = p1[r] + cb1;
                }
            }
        }
        __syncthreads();
    }
}

// ---------------------------------------------------------------------------
static void build_csr(const int* rows, const int* cols, const float* vals, int nnz,
                      int nrows, int* cnt, int* ptr, int* cur, int* bsum, int2* edges) {
    int n = nrows + 1;
    int sblocks = (n + 1023) / 1024;
    zero_int_kernel<<<(n + 255) / 256, 256>>>(cnt, n);
    hist_kernel<<<(nnz / 4 + 255) / 256, 256>>>(rows, nnz, cnt);
    scan_local_kernel<<<sblocks, 1024>>>(cnt, ptr, bsum, n);
    scan_add_kernel<<<sblocks, 1024>>>(ptr, cur, bsum, n, sblocks);
    scatter_kernel<<<(nnz / 4 + 255) / 256, 256>>>(rows, cols, vals, nnz, cur, edges);
}

extern "C" void kernel_launch(void* const* d_in, const int* in_sizes, int n_in,
                              void* d_out, int out_size) {
    const int*   A_row  = (const int*)d_in[0];
    const int*   A_col  = (const int*)d_in[1];
    const float* A_val  = (const float*)d_in[2];
    const int*   X_row  = (const int*)d_in[3];
    const int*   X_col  = (const int*)d_in[4];
    const float* X_val  = (const float*)d_in[5];
    const float* emb_W  = (const float*)d_in[6];
    const float* lin1_W = (const float*)d_in[7];
    const float* lin2_W = (const float*)d_in[8];
    const float* norm_g = (const float*)d_in[9];
    const float* norm_b = (const float*)d_in[10];
    const float* mlp_W  = (const float*)d_in[11];
    const float* mlp_b  = (const float*)d_in[12];
    const float* clf_W  = (const float*)d_in[13];
    const float* clf_b  = (const float*)d_in[14];
    float* out = (float*)d_out;

    int E     = in_sizes[0];
    int NNZ   = in_sizes[3];
    int V     = in_sizes[6] / H;
    int NDOCS = out_size / 2;

    cudaFuncSetAttribute(gemm_relu_h_kernel, cudaFuncAttributeMaxDynamicSharedMemorySize, GEMM_SMEM);
    cudaFuncSetAttribute(gemm_ln_h_kernel,   cudaFuncAttributeMaxDynamicSharedMemorySize, GEMM_SMEM);
    cudaFuncSetAttribute(head_kernel,        cudaFuncAttributeMaxDynamicSharedMemorySize, GEMM_SMEM);

    float  *F;
    __half *Dh;
    int *cnt, *ptr, *cur, *bsum;
    int2 *edges;
    cudaGetSymbolAddress((void**)&F, g_F);
    cudaGetSymbolAddress((void**)&Dh, g_Dh);
    cudaGetSymbolAddress((void**)&cnt, g_cnt);
    cudaGetSymbolAddress((void**)&ptr, g_ptr);
    cudaGetSymbolAddress((void**)&cur, g_cur);
    cudaGetSymbolAddress((void**)&bsum, g_bsum);
    cudaGetSymbolAddress((void**)&edges, g_edges);

    const int GRID = 296;
    int spmmA_grid = (V + 7) / 8;
    int spmmX_grid = (NDOCS + 7) / 8;

    // CSR(A) — reused by both A-spmms
    build_csr(A_row, A_col, A_val, E, V, cnt, ptr, cur, bsum, edges);
    // emb -> fp16
    f2h_kernel<<<(V * 32 + 255) / 256, 256>>>(emb_W, Dh, V * 32);
    // 1) F = A @ emb_h
    spmm_h_kernel<<<spmmA_grid, 256>>>(ptr, edges, Dh, F, V);
    // 2) Dh = fp16(relu(F @ lin1^T))
    gemm_relu_h_kernel<<<GRID, GEMM_THREADS, GEMM_SMEM>>>(F, lin1_W, Dh, V);
    // 3) F = A @ Dh
    spmm_h_kernel<<<spmmA_grid, 256>>>(ptr, edges, Dh, F, V);
    // 4) Dh = fp16( layernorm(0.3*emb + 0.7*relu(F @ lin2^T)) + emb )
    gemm_ln_h_kernel<<<GRID, GEMM_THREADS, GEMM_SMEM>>>(F, lin2_W, emb_W, norm_g, norm_b, Dh, V);
    // CSR(X)
    build_csr(X_row, X_col, X_val, NNZ, NDOCS, cnt, ptr, cur, bsum, edges);
    // 5) F = X @ Dh  (Dh carries +emb, folding both X-spmms)
    spmm_h_kernel<<<spmmX_grid, 256>>>(ptr, edges, Dh, F, NDOCS);
    // 6) logits
    head_kernel<<<GRID, GEMM_THREADS, GEMM_SMEM>>>(F, mlp_W, mlp_b, clf_W, clf_b, out, NDOCS);
}

// round 6
// speedup vs baseline: 2.1772x; 1.2165x over previous
#include <cuda_runtime.h>
#include <cuda_fp16.h>

#define H 128
#define VMAX 50000
#define EMAX 1600000
#define SPITCH 272                            // halfs/row: 136 words, ≡8 mod 32 banks
#define TG_SMEM (2 * 128 * SPITCH * 2)        // W(hi|lo) + in(hi|lo), 139264 B

// Scratch (device globals: no allocation allowed)
__device__ float  g_F[VMAX * H];        // fp32 spmm output / gemm input
__device__ __half g_Dh[VMAX * H];       // fp16 gather operand / gemm output
__device__ int2   g_edges[EMAX];
__device__ int    g_cnt[VMAX + 1];
__device__ int    g_ptr[VMAX + 1];
__device__ int    g_cur[VMAX + 1];
__device__ int    g_bsum[64];

// ---------------------------------------------------------------------------
// CSR build
// ---------------------------------------------------------------------------
__global__ void zero_int_kernel(int* __restrict__ p, int n) {
    int i = blockIdx.x * blockDim.x + threadIdx.x;
    if (i < n) p[i] = 0;
}

__global__ void hist_kernel(const int* __restrict__ rows, int nnz, int* __restrict__ cnt) {
    int base = (blockIdx.x * blockDim.x + threadIdx.x) * 4;
    if (base + 4 <= nnz) {
        int4 r4 = *(const int4*)(rows + base);
        atomicAdd(&cnt[r4.x], 1);
        atomicAdd(&cnt[r4.y], 1);
        atomicAdd(&cnt[r4.z], 1);
        atomicAdd(&cnt[r4.w], 1);
    } else {
        for (int e = base; e < nnz; e++) atomicAdd(&cnt[__ldg(rows + e)], 1);
    }
}

__global__ void scan_local_kernel(const int* __restrict__ cnt, int* __restrict__ loc,
                                  int* __restrict__ bsum, int n) {
    __shared__ int sm[1024];
    int i = blockIdx.x * 1024 + threadIdx.x;
    int v = (i < n) ? cnt[i] : 0;
    sm[threadIdx.x] = v;
    __syncthreads();
    #pragma unroll
    for (int off = 1; off < 1024; off <<= 1) {
        int add = (threadIdx.x >= off) ? sm[threadIdx.x - off] : 0;
        __syncthreads();
        sm[threadIdx.x] += add;
        __syncthreads();
    }
    if (i < n) loc[i] = sm[threadIdx.x] - v;
    if (threadIdx.x == 1023) bsum[blockIdx.x] = sm[1023];
}

__global__ void scan_add_kernel(int* __restrict__ ptr, int* __restrict__ cur,
                                const int* __restrict__ bsum, int n, int nb) {
    __shared__ int sb[64];
    int t = threadIdx.x;
    if (t < 64) sb[t] = (t < nb) ? bsum[t] : 0;
    __syncthreads();
    if (t == 0) {
        int run = 0;
        for (int i = 0; i < 64; i++) { int v = sb[i]; sb[i] = run; run += v; }
    }
    __syncthreads();
    int i = blockIdx.x * 1024 + t;
    if (i < n) {
        int v = ptr[i] + sb[blockIdx.x];
        ptr[i] = v;
        cur[i] = v;
    }
}

__global__ void scatter_kernel(const int* __restrict__ rows, const int* __restrict__ cols,
                               const float* __restrict__ vals, int nnz,
                               int* __restrict__ cur, int2* __restrict__ edges) {
    int base = (blockIdx.x * blockDim.x + threadIdx.x) * 4;
    if (base + 4 <= nnz) {
        int4   r4 = *(const int4*)(rows + base);
        int4   c4 = *(const int4*)(cols + base);
        float4 v4 = *(const float4*)(vals + base);
        int p0 = atomicAdd(&cur[r4.x], 1);
        int p1 = atomicAdd(&cur[r4.y], 1);
        int p2 = atomicAdd(&cur[r4.z], 1);
        int p3 = atomicAdd(&cur[r4.w], 1);
        edges[p0] = make_int2(c4.x, __float_as_int(v4.x));
        edges[p1] = make_int2(c4.y, __float_as_int(v4.y));
        edges[p2] = make_int2(c4.z, __float_as_int(v4.z));
        edges[p3] = make_int2(c4.w, __float_as_int(v4.w));
    } else {
        for (int e = base; e < nnz; e++) {
            int r = __ldg(rows + e);
            int p = atomicAdd(&cur[r], 1);
            edges[p] = make_int2(__ldg(cols + e), __float_as_int(__ldg(vals + e)));
        }
    }
}

// ---------------------------------------------------------------------------
__global__ void f2h_kernel(const float* __restrict__ src, __half* __restrict__ dst, int n4) {
    int i = blockIdx.x * blockDim.x + threadIdx.x;
    if (i < n4) {
        float4 v = ((const float4*)src)[i];
        __half2* d = (__half2*)dst;
        d[2 * i]     = __floats2half2_rn(v.x, v.y);
        d[2 * i + 1] = __floats2half2_rn(v.z, v.w);
    }
}

// ---------------------------------------------------------------------------
// CSR SpMM: fp16 gather, fp32 accumulate + output. Warp per row.
// ---------------------------------------------------------------------------
__device__ __forceinline__ void acc_h(float4& acc, float v, uint2 d) {
    float2 f0 = __half22float2(*reinterpret_cast<__half2*>(&d.x));
    float2 f1 = __half22float2(*reinterpret_cast<__half2*>(&d.y));
    acc.x += v * f0.x; acc.y += v * f0.y; acc.z += v * f1.x; acc.w += v * f1.y;
}

__global__ void spmm_h_kernel(const int* __restrict__ ptr, const int2* __restrict__ edges,
                              const __half* __restrict__ dense, float* __restrict__ out,
                              int nrows) {
    int r = (blockIdx.x * blockDim.x + threadIdx.x) >> 5;
    if (r >= nrows) return;
    int lane = threadIdx.x & 31;
    int s = __ldg(ptr + r);
    int e = __ldg(ptr + r + 1);
    float4 acc = make_float4(0.f, 0.f, 0.f, 0.f);
    const uint2* db = (const uint2*)dense;
    int i = s;
    for (; i + 4 <= e; i += 4) {
        int2 m0 = __ldg(edges + i);
        int2 m1 = __ldg(edges + i + 1);
        int2 m2 = __ldg(edges + i + 2);
        int2 m3 = __ldg(edges + i + 3);
        uint2 d0 = __ldg(db + (size_t)m0.x * 32 + lane);
        uint2 d1 = __ldg(db + (size_t)m1.x * 32 + lane);
        uint2 d2 = __ldg(db + (size_t)m2.x * 32 + lane);
        uint2 d3 = __ldg(db + (size_t)m3.x * 32 + lane);
        acc_h(acc, __int_as_float(m0.y), d0);
        acc_h(acc, __int_as_float(m1.y), d1);
        acc_h(acc, __int_as_float(m2.y), d2);
        acc_h(acc, __int_as_float(m3.y), d3);
    }
    for (; i < e; i++) {
        int2 m = __ldg(edges + i);
        uint2 d = __ldg(db + (size_t)m.x * 32 + lane);
        acc_h(acc, __int_as_float(m.y), d);
    }
    ((float4*)(out + (size_t)r * H))[lane] = acc;
}

// ---------------------------------------------------------------------------
// Split-fp16 tensor GEMM: out = in @ W^T, fp32-accurate via 3-term HMMA.
// smem layout (both in & W): row-major, interleaved hi/lo at 2-half grain:
//   elem (row, k): hi half at row*SPITCH + (k>>1)*4 + (k&1), lo at +2.
// One uint2 LDS.64 fetches {hi2, lo2} for a k-pair. Pitch 136 words ≡ 8 mod 32
// banks -> 16-lane phases (grp 0..7, qp 0..3 -> 8*grp + 2*qp words) conflict-free.
// Tile: 128 rows x 128 cols; warp w owns rows [w*16, w*16+16).
// c-frag lane(grp=l>>2,qp=l&3): rows {grp, grp+8}, cols {nt*8+qp*2, +1}.
// ---------------------------------------------------------------------------
__device__ __forceinline__ void mma_16816(float4& d, unsigned a0, unsigned a1,
                                          unsigned a2, unsigned a3,
                                          unsigned b0, unsigned b1) {
    asm volatile(
        "mma.sync.aligned.m16n8k16.row.col.f32.f16.f16.f32 "
        "{%0,%1,%2,%3}, {%4,%5,%6,%7}, {%8,%9}, {%0,%1,%2,%3};"
        : "+f"(d.x), "+f"(d.y), "+f"(d.z), "+f"(d.w)
        : "r"(a0), "r"(a1), "r"(a2), "r"(a3), "r"(b0), "r"(b1));
}

__device__ __forceinline__ void split_store(__half* S, int row, int kpair, float x, float y) {
    __half hx = __float2half_rn(x);
    __half hy = __float2half_rn(y);
    float lx = x - __half2float(hx);
    float ly = y - __half2float(hy);
    __half2* p = (__half2*)(S + row * SPITCH + kpair * 4);
    p[0] = __halves2half2(hx, hy);
    p[1] = __floats2half2_rn(lx, ly);
}

__device__ __forceinline__ void tg_load_W(const float* __restrict__ W, __half* Ws, int t) {
    for (int idx = t; idx < 8192; idx += 256) {
        int j = idx >> 6, kp = idx & 63;
        float2 w = ((const float2*)W)[idx];
        split_store(Ws, j, kp, w.x, w.y);
    }
}

__device__ __forceinline__ void tg_load_in(const float* __restrict__ in, __half* inS,
                                           int row0, int N, int t) {
    for (int idx = t; idx < 8192; idx += 256) {
        int r = idx >> 6, kp = idx & 63;
        float2 v = make_float2(0.f, 0.f);
        if (row0 + r < N) v = ((const float2*)(in + (size_t)(row0 + r) * H))[kp];
        split_store(inS, r, kp, v.x, v.y);
    }
}

__device__ __forceinline__ void tg_compute(const __half* inS, const __half* Ws,
                                           int warp, int grp, int qp, float4 (&acc)[16]) {
    #pragma unroll
    for (int nt = 0; nt < 16; nt++) acc[nt] = make_float4(0.f, 0.f, 0.f, 0.f);
    const __half* ab = inS + (warp * 16 + grp) * SPITCH + qp * 4;
    const __half* bb = Ws + grp * SPITCH + qp * 4;
    #pragma unroll
    for (int ks = 0; ks < 8; ks++) {
        // k offset ks*16 -> kpair ks*8 -> ks*32 halfs; cols+8 -> +16 halfs
        uint2 aA = *(const uint2*)(ab + ks * 32);                 // {a0_hi, a0_lo}
        uint2 aB = *(const uint2*)(ab + 8 * SPITCH + ks * 32);    // {a1_hi, a1_lo}
        uint2 aC = *(const uint2*)(ab + ks * 32 + 16);            // {a2_hi, a2_lo}
        uint2 aD = *(const uint2*)(ab + 8 * SPITCH + ks * 32 + 16);
        #pragma unroll
        for (int nt = 0; nt < 16; nt++) {
            uint2 b0 = *(const uint2*)(bb + nt * 8 * SPITCH + ks * 32);
            uint2 b1 = *(const uint2*)(bb + nt * 8 * SPITCH + ks * 32 + 16);
            mma_16816(acc[nt], aA.x, aB.x, aC.x, aD.x, b0.x, b1.x);  // hi*hi
            mma_16816(acc[nt], aA.x, aB.x, aC.x, aD.x, b0.y, b1.y);  // hi*lo
            mma_16816(acc[nt], aA.y, aB.y, aC.y, aD.y, b0.x, b1.x);  // lo*hi
        }
    }
}

// K1: outh = f16(relu(in @ W^T))
__global__ void __launch_bounds__(256)
tgemm_relu(const float* __restrict__ in, const float* __restrict__ W,
           __half* __restrict__ outh, int N) {
    extern __shared__ __half smh[];
    __half* Ws = smh;
    __half* inS = smh + 128 * SPITCH;
    int t = threadIdx.x, lane = t & 31, warp = t >> 5;
    int grp = lane >> 2, qp = lane & 3;
    tg_load_W(W, Ws, t);
    int row0 = blockIdx.x * 128;
    tg_load_in(in, inS, row0, N, t);
    __syncthreads();
    float4 acc[16];
    tg_compute(inS, Ws, warp, grp, qp, acc);
    int r0 = row0 + warp * 16 + grp, r1 = r0 + 8;
    #pragma unroll
    for (int nt = 0; nt < 16; nt++) {
        int col = nt * 8 + qp * 2;
        if (r0 < N)
            *(__half2*)(outh + (size_t)r0 * H + col) =
                __floats2half2_rn(fmaxf(acc[nt].x, 0.f), fmaxf(acc[nt].y, 0.f));
        if (r1 < N)
            *(__half2*)(outh + (size_t)r1 * H + col) =
                __floats2half2_rn(fmaxf(acc[nt].z, 0.f), fmaxf(acc[nt].w, 0.f));
    }
}

// K2: outh = f16( layernorm(0.3*emb + 0.7*relu(in @ W^T)) + emb )
__global__ void __launch_bounds__(256)
tgemm_ln(const float* __restrict__ in, const float* __restrict__ W,
         const float* __restrict__ emb,
         const float* __restrict__ norm_g, const float* __restrict__ norm_b,
         __half* __restrict__ outh, int N) {
    extern __shared__ __half smh[];
    __half* Ws = smh;
    __half* inS = smh + 128 * SPITCH;
    int t = threadIdx.x, lane = t & 31, warp = t >> 5;
    int grp = lane >> 2, qp = lane & 3;
    tg_load_W(W, Ws, t);
    int row0 = blockIdx.x * 128;
    tg_load_in(in, inS, row0, N, t);
    __syncthreads();
    float4 acc[16];
    tg_compute(inS, Ws, warp, grp, qp, acc);

    int r0 = row0 + warp * 16 + grp, r1 = r0 + 8;
    float s0 = 0.f, q0 = 0.f, s1 = 0.f, q1 = 0.f;
    #pragma unroll
    for (int nt = 0; nt < 16; nt++) {
        int col = nt * 8 + qp * 2;
        float2 e0 = (r0 < N) ? *(const float2*)(emb + (size_t)r0 * H + col) : make_float2(0.f, 0.f);
        float2 e1 = (r1 < N) ? *(const float2*)(emb + (size_t)r1 * H + col) : make_float2(0.f, 0.f);
        float z0x = 0.3f * e0.x + 0.7f * fmaxf(acc[nt].x, 0.f);
        float z0y = 0.3f * e0.y + 0.7f * fmaxf(acc[nt].y, 0.f);
        float z1x = 0.3f * e1.x + 0.7f * fmaxf(acc[nt].z, 0.f);
        float z1y = 0.3f * e1.y + 0.7f * fmaxf(acc[nt].w, 0.f);
        acc[nt] = make_float4(z0x, z0y, z1x, z1y);
        s0 += z0x + z0y; q0 += z0x * z0x + z0y * z0y;
        s1 += z1x + z1y; q1 += z1x * z1x + z1y * z1y;
    }
    #pragma unroll
    for (int off = 1; off < 4; off <<= 1) {
        s0 += __shfl_xor_sync(0xffffffffu, s0, off);
        q0 += __shfl_xor_sync(0xffffffffu, q0, off);
        s1 += __shfl_xor_sync(0xffffffffu, s1, off);
        q1 += __shfl_xor_sync(0xffffffffu, q1, off);
    }
    float m0 = s0 * (1.f / 128.f), m1 = s1 * (1.f / 128.f);
    float i0 = rsqrtf(q0 * (1.f / 128.f) - m0 * m0 + 1e-5f);
    float i1 = rsqrtf(q1 * (1.f / 128.f) - m1 * m1 + 1e-5f);
    #pragma unroll
    for (int nt = 0; nt < 16; nt++) {
        int col = nt * 8 + qp * 2;
        float2 g2 = *(const float2*)(norm_g + col);
        float2 b2 = *(const float2*)(norm_b + col);
        if (r0 < N) {
            float2 e0 = *(const float2*)(emb + (size_t)r0 * H + col);
            float vx = (acc[nt].x - m0) * i0 * g2.x + b2.x + e0.x;
            float vy = (acc[nt].y - m0) * i0 * g2.y + b2.y + e0.y;
            *(__half2*)(outh + (size_t)r0 * H + col) = __floats2half2_rn(vx, vy);
        }
        if (r1 < N) {
            float2 e1 = *(const float2*)(emb + (size_t)r1 * H + col);
            float vx = (acc[nt].z - m1) * i1 * g2.x + b2.x + e1.x;
            float vy = (acc[nt].w - m1) * i1 * g2.y + b2.y + e1.y;
            *(__half2*)(outh + (size_t)r1 * H + col) = __floats2half2_rn(vx, vy);
        }
    }
}

// K3: logits = relu(in @ mlpW^T + mlp_b) @ clfW^T + clf_b
__global__ void __launch_bounds__(256)
tgemm_head(const float* __restrict__ in, const float* __restrict__ W,
           const float* __restrict__ mlp_b,
           const float* __restrict__ clf_W, const float* __restrict__ clf_b,
           float* __restrict__ out, int N) {
    extern __shared__ __half smh[];
    __half* Ws = smh;
    __half* inS = smh + 128 * SPITCH;
    int t = threadIdx.x, lane = t & 31, warp = t >> 5;
    int grp = lane >> 2, qp = lane & 3;
    tg_load_W(W, Ws, t);
    int row0 = blockIdx.x * 128;
    tg_load_in(in, inS, row0, N, t);
    __syncthreads();
    float4 acc[16];
    tg_compute(inS, Ws, warp, grp, qp, acc);

    int r0 = row0 + warp * 16 + grp, r1 = r0 + 8;
    float p00 = 0.f, p01 = 0.f, p10 = 0.f, p11 = 0.f;
    #pragma unroll
    for (int nt = 0; nt < 16; nt++) {
        int col = nt * 8 + qp * 2;
        float2 mb = *(const float2*)(mlp_b + col);
        float2 c0 = *(const float2*)(clf_W + col);
        float2 c1 = *(const float2*)(clf_W + H + col);
        float h0x = fmaxf(acc[nt].x + mb.x, 0.f), h0y = fmaxf(acc[nt].y + mb.y, 0.f);
        float h1x = fmaxf(acc[nt].z + mb.x, 0.f), h1y = fmaxf(acc[nt].w + mb.y, 0.f);
        p00 += h0x * c0.x + h0y * c0.y;  p01 += h0x * c1.x + h0y * c1.y;
        p10 += h1x * c0.x + h1y * c0.y;  p11 += h1x * c1.x + h1y * c1.y;
    }
    #pragma unroll
    for (int off = 1; off < 4; off <<= 1) {
        p00 += __shfl_xor_sync(0xffffffffu, p00, off);
        p01 += __shfl_xor_sync(0xffffffffu, p01, off);
        p10 += __shfl_xor_sync(0xffffffffu, p10, off);
        p11 += __shfl_xor_sync(0xffffffffu, p11, off);
    }
    if (qp == 0) {
        float cb0 = clf_b[0], cb1 = clf_b[1];
        if (r0 < N) { out[(size_t)r0 * 2] = p00 + cb0; out[(size_t)r0 * 2 + 1] = p01 + cb1; }
        if (r1 < N) { out[(size_t)r1 * 2] = p10 + cb0; out[(size_t)r1 * 2 + 1] = p11 + cb1; }
    }
}

// ---------------------------------------------------------------------------
static void build_csr(const int* rows, const int* cols, const float* vals, int nnz,
                      int nrows, int* cnt, int* ptr, int* cur, int* bsum, int2* edges) {
    int n = nrows + 1;
    int sblocks = (n + 1023) / 1024;
    zero_int_kernel<<<(n + 255) / 256, 256>>>(cnt, n);
    hist_kernel<<<(nnz / 4 + 255) / 256, 256>>>(rows, nnz, cnt);
    scan_local_kernel<<<sblocks, 1024>>>(cnt, ptr, bsum, n);
    scan_add_kernel<<<sblocks, 1024>>>(ptr, cur, bsum, n, sblocks);
    scatter_kernel<<<(nnz / 4 + 255) / 256, 256>>>(rows, cols, vals, nnz, cur, edges);
}

extern "C" void kernel_launch(void* const* d_in, const int* in_sizes, int n_in,
                              void* d_out, int out_size) {
    const int*   A_row  = (const int*)d_in[0];
    const int*   A_col  = (const int*)d_in[1];
    const float* A_val  = (const float*)d_in[2];
    const int*   X_row  = (const int*)d_in[3];
    const int*   X_col  = (const int*)d_in[4];
    const float* X_val  = (const float*)d_in[5];
    const float* emb_W  = (const float*)d_in[6];
    const float* lin1_W = (const float*)d_in[7];
    const float* lin2_W = (const float*)d_in[8];
    const float* norm_g = (const float*)d_in[9];
    const float* norm_b = (const float*)d_in[10];
    const float* mlp_W  = (const float*)d_in[11];
    const float* mlp_b  = (const float*)d_in[12];
    const float* clf_W  = (const float*)d_in[13];
    const float* clf_b  = (const float*)d_in[14];
    float* out = (float*)d_out;

    int E     = in_sizes[0];
    int NNZ   = in_sizes[3];
    int V     = in_sizes[6] / H;
    int NDOCS = out_size / 2;

    cudaFuncSetAttribute(tgemm_relu, cudaFuncAttributeMaxDynamicSharedMemorySize, TG_SMEM);
    cudaFuncSetAttribute(tgemm_ln,   cudaFuncAttributeMaxDynamicSharedMemorySize, TG_SMEM);
    cudaFuncSetAttribute(tgemm_head, cudaFuncAttributeMaxDynamicSharedMemorySize, TG_SMEM);

    float  *F;
    __half *Dh;
    int *cnt, *ptr, *cur, *bsum;
    int2 *edges;
    cudaGetSymbolAddress((void**)&F, g_F);
    cudaGetSymbolAddress((void**)&Dh, g_Dh);
    cudaGetSymbolAddress((void**)&cnt, g_cnt);
    cudaGetSymbolAddress((void**)&ptr, g_ptr);
    cudaGetSymbolAddress((void**)&cur, g_cur);
    cudaGetSymbolAddress((void**)&bsum, g_bsum);
    cudaGetSymbolAddress((void**)&edges, g_edges);

    int spmmA_grid = (V + 7) / 8;
    int spmmX_grid = (NDOCS + 7) / 8;
    int tgV_grid   = (V + 127) / 128;
    int tgD_grid   = (NDOCS + 127) / 128;

    // CSR(A) — reused by both A-spmms
    build_csr(A_row, A_col, A_val, E, V, cnt, ptr, cur, bsum, edges);
    // emb -> fp16 gather operand
    f2h_kernel<<<(V * 32 + 255) / 256, 256>>>(emb_W, Dh, V * 32);
    // 1) F = A @ Dh
    spmm_h_kernel<<<spmmA_grid, 256>>>(ptr, edges, Dh, F, V);
    // 2) Dh = f16(relu(F @ lin1^T))      [split-fp16 tensor GEMM, fp32-accurate]
    tgemm_relu<<<tgV_grid, 256, TG_SMEM>>>(F, lin1_W, Dh, V);
    // 3) F = A @ Dh
    spmm_h_kernel<<<spmmA_grid, 256>>>(ptr, edges, Dh, F, V);
    // 4) Dh = f16( layernorm(0.3*emb + 0.7*relu(F @ lin2^T)) + emb )
    tgemm_ln<<<tgV_grid, 256, TG_SMEM>>>(F, lin2_W, emb_W, norm_g, norm_b, Dh, V);
    // CSR(X)
    build_csr(X_row, X_col, X_val, NNZ, NDOCS, cnt, ptr, cur, bsum, edges);
    // 5) F = X @ Dh   (Dh carries +emb, folding both X-spmms)
    spmm_h_kernel<<<spmmX_grid, 256>>>(ptr, edges, Dh, F, NDOCS);
    // 6) logits
    tgemm_head<<<tgD_grid, 256, TG_SMEM>>>(F, mlp_W, mlp_b, clf_W, clf_b, out, NDOCS);
}

// round 7
// speedup vs baseline: 2.2612x; 1.0386x over previous
#include <cuda_runtime.h>
#include <cuda_fp16.h>

#define H 128
#define VMAX 50000
#define NDOCS_MAX 20000
#define EMAX_ALL 3200000                      // A edges + X edges combined
#define NCNT (VMAX + NDOCS_MAX + 2)
#define SPITCH 272                            // halfs/row: 136 words, ≡8 mod 32 banks
#define TG_SMEM (2 * 128 * SPITCH * 2)        // W(hi|lo) + in(hi|lo), 139264 B

// Scratch (device globals: no allocation allowed)
__device__ float  g_F[VMAX * H];        // fp32 spmm output / gemm input
__device__ __half g_Dh[VMAX * H];       // fp16 gather operand / gemm output
__device__ int2   g_edges[EMAX_ALL];    // combined CSR edges: A then X
__device__ int    g_cnt[NCNT];
__device__ int    g_ptr[NCNT];
__device__ int    g_cur[NCNT];
__device__ int    g_bsum[128];

// ---------------------------------------------------------------------------
// Merged CSR build (A and X in one pass set)
// counts layout: [0,V) = A rows, [V, V+NDOCS) = X rows, +1 sentinel.
// After combined exclusive scan: ptr[V] == E, ptr[V+NDOCS] == E+NNZ, so
// spmm_A uses (ptr, edges) and spmm_X uses (ptr+V, edges) with absolute idx.
// ---------------------------------------------------------------------------
__global__ void zero_int_kernel(int* __restrict__ p, int n) {
    int i = blockIdx.x * blockDim.x + threadIdx.x;
    if (i < n) p[i] = 0;
}

__global__ void hist_merged_kernel(const int* __restrict__ A_row, int E,
                                   const int* __restrict__ X_row, int NNZ,
                                   int* __restrict__ cnt, int V) {
    int tid = blockIdx.x * blockDim.x + threadIdx.x;
    int nA = (E + 3) / 4;
    if (tid < nA) {
        int base = tid * 4;
        if (base + 4 <= E) {
            int4 r4 = *(const int4*)(A_row + base);
            atomicAdd(&cnt[r4.x], 1);
            atomicAdd(&cnt[r4.y], 1);
            atomicAdd(&cnt[r4.z], 1);
            atomicAdd(&cnt[r4.w], 1);
        } else {
            for (int e = base; e < E; e++) atomicAdd(&cnt[__ldg(A_row + e)], 1);
        }
    } else {
        int base = (tid - nA) * 4;
        if (base + 4 <= NNZ) {
            int4 r4 = *(const int4*)(X_row + base);
            atomicAdd(&cnt[V + r4.x], 1);
            atomicAdd(&cnt[V + r4.y], 1);
            atomicAdd(&cnt[V + r4.z], 1);
            atomicAdd(&cnt[V + r4.w], 1);
        } else {
            for (int e = base; e < NNZ; e++) atomicAdd(&cnt[V + __ldg(X_row + e)], 1);
        }
    }
}

__global__ void scan_local_kernel(const int* __restrict__ cnt, int* __restrict__ loc,
                                  int* __restrict__ bsum, int n) {
    __shared__ int sm[1024];
    int i = blockIdx.x * 1024 + threadIdx.x;
    int v = (i < n) ? cnt[i] : 0;
    sm[threadIdx.x] = v;
    __syncthreads();
    #pragma unroll
    for (int off = 1; off < 1024; off <<= 1) {
        int add = (threadIdx.x >= off) ? sm[threadIdx.x - off] : 0;
        __syncthreads();
        sm[threadIdx.x] += add;
        __syncthreads();
    }
    if (i < n) loc[i] = sm[threadIdx.x] - v;
    if (threadIdx.x == 1023) bsum[blockIdx.x] = sm[1023];
}

__global__ void scan_add_kernel(int* __restrict__ ptr, int* __restrict__ cur,
                                const int* __restrict__ bsum, int n, int nb) {
    __shared__ int sb[128];
    int t = threadIdx.x;
    if (t < 128) sb[t] = (t < nb) ? bsum[t] : 0;
    __syncthreads();
    if (t == 0) {
        int run = 0;
        for (int i = 0; i < 128; i++) { int v = sb[i]; sb[i] = run; run += v; }
    }
    __syncthreads();
    int i = blockIdx.x * 1024 + t;
    if (i < n) {
        int v = ptr[i] + sb[blockIdx.x];
        ptr[i] = v;
        cur[i] = v;
    }
}

__global__ void scatter_merged_kernel(const int* __restrict__ A_row, const int* __restrict__ A_col,
                                      const float* __restrict__ A_val, int E,
                                      const int* __restrict__ X_row, const int* __restrict__ X_col,
                                      const float* __restrict__ X_val, int NNZ,
                                      int* __restrict__ cur, int2* __restrict__ edges, int V) {
    int tid = blockIdx.x * blockDim.x + threadIdx.x;
    int nA = (E + 3) / 4;
    if (tid < nA) {
        int base = tid * 4;
        if (base + 4 <= E) {
            int4   r4 = *(const int4*)(A_row + base);
            int4   c4 = *(const int4*)(A_col + base);
            float4 v4 = *(const float4*)(A_val + base);
            int p0 = atomicAdd(&cur[r4.x], 1);
            int p1 = atomicAdd(&cur[r4.y], 1);
            int p2 = atomicAdd(&cur[r4.z], 1);
            int p3 = atomicAdd(&cur[r4.w], 1);
            edges[p0] = make_int2(c4.x, __float_as_int(v4.x));
            edges[p1] = make_int2(c4.y, __float_as_int(v4.y));
            edges[p2] = make_int2(c4.z, __float_as_int(v4.z));
            edges[p3] = make_int2(c4.w, __float_as_int(v4.w));
        } else {
            for (int e = base; e < E; e++) {
                int p = atomicAdd(&cur[__ldg(A_row + e)], 1);
                edges[p] = make_int2(__ldg(A_col + e), __float_as_int(__ldg(A_val + e)));
            }
        }
    } else {
        int base = (tid - nA) * 4;
        if (base + 4 <= NNZ) {
            int4   r4 = *(const int4*)(X_row + base);
            int4   c4 = *(const int4*)(X_col + base);
            float4 v4 = *(const float4*)(X_val + base);
            int p0 = atomicAdd(&cur[V + r4.x], 1);
            int p1 = atomicAdd(&cur[V + r4.y], 1);
            int p2 = atomicAdd(&cur[V + r4.z], 1);
            int p3 = atomicAdd(&cur[V + r4.w], 1);
            edges[p0] = make_int2(c4.x, __float_as_int(v4.x));
            edges[p1] = make_int2(c4.y, __float_as_int(v4.y));
            edges[p2] = make_int2(c4.z, __float_as_int(v4.z));
            edges[p3] = make_int2(c4.w, __float_as_int(v4.w));
        } else {
            for (int e = base; e < NNZ; e++) {
                int p = atomicAdd(&cur[V + __ldg(X_row + e)], 1);
                edges[p] = make_int2(__ldg(X_col + e), __float_as_int(__ldg(X_val + e)));
            }
        }
    }
}

// ---------------------------------------------------------------------------
__global__ void f2h_kernel(const float* __restrict__ src, __half* __restrict__ dst, int n4) {
    int i = blockIdx.x * blockDim.x + threadIdx.x;
    if (i < n4) {
        float4 v = ((const float4*)src)[i];
        __half2* d = (__half2*)dst;
        d[2 * i]     = __floats2half2_rn(v.x, v.y);
        d[2 * i + 1] = __floats2half2_rn(v.z, v.w);
    }
}

// ---------------------------------------------------------------------------
// CSR SpMM: fp16 gather, fp32 accumulate + output. Warp per row, 8-deep ILP.
// ---------------------------------------------------------------------------
__device__ __forceinline__ void acc_h(float4& acc, float v, uint2 d) {
    float2 f0 = __half22float2(*reinterpret_cast<__half2*>(&d.x));
    float2 f1 = __half22float2(*reinterpret_cast<__half2*>(&d.y));
    acc.x += v * f0.x; acc.y += v * f0.y; acc.z += v * f1.x; acc.w += v * f1.y;
}

__global__ void spmm_h_kernel(const int* __restrict__ ptr, const int2* __restrict__ edges,
                              const __half* __restrict__ dense, float* __restrict__ out,
                              int nrows) {
    int r = (blockIdx.x * blockDim.x + threadIdx.x) >> 5;
    if (r >= nrows) return;
    int lane = threadIdx.x & 31;
    int s = __ldg(ptr + r);
    int e = __ldg(ptr + r + 1);
    float4 acc = make_float4(0.f, 0.f, 0.f, 0.f);
    const uint2* db = (const uint2*)dense;
    int i = s;
    for (; i + 8 <= e; i += 8) {
        int2 m[8];
        uint2 d[8];
        #pragma unroll
        for (int k = 0; k < 8; k++) m[k] = __ldg(edges + i + k);
        #pragma unroll
        for (int k = 0; k < 8; k++) d[k] = __ldg(db + (size_t)m[k].x * 32 + lane);
        #pragma unroll
        for (int k = 0; k < 8; k++) acc_h(acc, __int_as_float(m[k].y), d[k]);
    }
    for (; i + 4 <= e; i += 4) {
        int2 m[4];
        uint2 d[4];
        #pragma unroll
        for (int k = 0; k < 4; k++) m[k] = __ldg(edges + i + k);
        #pragma unroll
        for (int k = 0; k < 4; k++) d[k] = __ldg(db + (size_t)m[k].x * 32 + lane);
        #pragma unroll
        for (int k = 0; k < 4; k++) acc_h(acc, __int_as_float(m[k].y), d[k]);
    }
    for (; i < e; i++) {
        int2 m = __ldg(edges + i);
        uint2 d = __ldg(db + (size_t)m.x * 32 + lane);
        acc_h(acc, __int_as_float(m.y), d);
    }
    ((float4*)(out + (size_t)r * H))[lane] = acc;
}

// ---------------------------------------------------------------------------
// Split-fp16 tensor GEMM: out = in @ W^T, fp32-accurate via 3-term HMMA.
// smem (in & W): row-major, hi/lo interleaved at 2-half grain:
//   elem (row,k): hi at row*SPITCH + (k>>1)*4 + (k&1), lo at +2.
// Pitch 136 words ≡ 8 mod 32 banks -> conflict-free fragment LDS.
// Tile 128x128; warp w owns rows [w*16, w*16+16).
// c-frag lane(grp=l>>2,qp=l&3): rows {grp, grp+8}, cols {nt*8+qp*2, +1}.
// ---------------------------------------------------------------------------
__device__ __forceinline__ void mma_16816(float4& d, unsigned a0, unsigned a1,
                                          unsigned a2, unsigned a3,
                                          unsigned b0, unsigned b1) {
    asm volatile(
        "mma.sync.aligned.m16n8k16.row.col.f32.f16.f16.f32 "
        "{%0,%1,%2,%3}, {%4,%5,%6,%7}, {%8,%9}, {%0,%1,%2,%3};"
        : "+f"(d.x), "+f"(d.y), "+f"(d.z), "+f"(d.w)
        : "r"(a0), "r"(a1), "r"(a2), "r"(a3), "r"(b0), "r"(b1));
}

__device__ __forceinline__ void split_store(__half* S, int row, int kpair, float x, float y) {
    __half hx = __float2half_rn(x);
    __half hy = __float2half_rn(y);
    float lx = x - __half2float(hx);
    float ly = y - __half2float(hy);
    __half2* p = (__half2*)(S + row * SPITCH + kpair * 4);
    p[0] = __halves2half2(hx, hy);
    p[1] = __floats2half2_rn(lx, ly);
}

__device__ __forceinline__ void tg_load_W(const float* __restrict__ W, __half* Ws, int t) {
    for (int idx = t; idx < 8192; idx += 256) {
        int j = idx >> 6, kp = idx & 63;
        float2 w = ((const float2*)W)[idx];
        split_store(Ws, j, kp, w.x, w.y);
    }
}

__device__ __forceinline__ void tg_load_in(const float* __restrict__ in, __half* inS,
                                           int row0, int N, int t) {
    for (int idx = t; idx < 8192; idx += 256) {
        int r = idx >> 6, kp = idx & 63;
        float2 v = make_float2(0.f, 0.f);
        if (row0 + r < N) v = ((const float2*)(in + (size_t)(row0 + r) * H))[kp];
        split_store(inS, r, kp, v.x, v.y);
    }
}

__device__ __forceinline__ void tg_compute(const __half* inS, const __half* Ws,
                                           int warp, int grp, int qp, float4 (&acc)[16]) {
    #pragma unroll
    for (int nt = 0; nt < 16; nt++) acc[nt] = make_float4(0.f, 0.f, 0.f, 0.f);
    const __half* ab = inS + (warp * 16 + grp) * SPITCH + qp * 4;
    const __half* bb = Ws + grp * SPITCH + qp * 4;
    #pragma unroll
    for (int ks = 0; ks < 8; ks++) {
        uint2 aA = *(const uint2*)(ab + ks * 32);
        uint2 aB = *(const uint2*)(ab + 8 * SPITCH + ks * 32);
        uint2 aC = *(const uint2*)(ab + ks * 32 + 16);
        uint2 aD = *(const uint2*)(ab + 8 * SPITCH + ks * 32 + 16);
        #pragma unroll
        for (int nt = 0; nt < 16; nt++) {
            uint2 b0 = *(const uint2*)(bb + nt * 8 * SPITCH + ks * 32);
            uint2 b1 = *(const uint2*)(bb + nt * 8 * SPITCH + ks * 32 + 16);
            mma_16816(acc[nt], aA.x, aB.x, aC.x, aD.x, b0.x, b1.x);  // hi*hi
            mma_16816(acc[nt], aA.x, aB.x, aC.x, aD.x, b0.y, b1.y);  // hi*lo
            mma_16816(acc[nt], aA.y, aB.y, aC.y, aD.y, b0.x, b1.x);  // lo*hi
        }
    }
}

// K1: outh = f16(relu(in @ W^T))
__global__ void __launch_bounds__(256)
tgemm_relu(const float* __restrict__ in, const float* __restrict__ W,
           __half* __restrict__ outh, int N) {
    extern __shared__ __half smh[];
    __half* Ws = smh;
    __half* inS = smh + 128 * SPITCH;
    int t = threadIdx.x, lane = t & 31, warp = t >> 5;
    int grp = lane >> 2, qp = lane & 3;
    tg_load_W(W, Ws, t);
    int row0 = blockIdx.x * 128;
    tg_load_in(in, inS, row0, N, t);
    __syncthreads();
    float4 acc[16];
    tg_compute(inS, Ws, warp, grp, qp, acc);
    int r0 = row0 + warp * 16 + grp, r1 = r0 + 8;
    #pragma unroll
    for (int nt = 0; nt < 16; nt++) {
        int col = nt * 8 + qp * 2;
        if (r0 < N)
            *(__half2*)(outh + (size_t)r0 * H + col) =
                __floats2half2_rn(fmaxf(acc[nt].x, 0.f), fmaxf(acc[nt].y, 0.f));
        if (r1 < N)
            *(__half2*)(outh + (size_t)r1 * H + col) =
                __floats2half2_rn(fmaxf(acc[nt].z, 0.f), fmaxf(acc[nt].w, 0.f));
    }
}

// K2: outh = f16( layernorm(0.3*emb + 0.7*relu(in @ W^T)) + emb )
__global__ void __launch_bounds__(256)
tgemm_ln(const float* __restrict__ in, const float* __restrict__ W,
         const float* __restrict__ emb,
         const float* __restrict__ norm_g, const float* __restrict__ norm_b,
         __half* __restrict__ outh, int N) {
    extern __shared__ __half smh[];
    __half* Ws = smh;
    __half* inS = smh + 128 * SPITCH;
    int t = threadIdx.x, lane = t & 31, warp = t >> 5;
    int grp = lane >> 2, qp = lane & 3;
    tg_load_W(W, Ws, t);
    int row0 = blockIdx.x * 128;
    tg_load_in(in, inS, row0, N, t);
    __syncthreads();
    float4 acc[16];
    tg_compute(inS, Ws, warp, grp, qp, acc);

    int r0 = row0 + warp * 16 + grp, r1 = r0 + 8;
    float s0 = 0.f, q0 = 0.f, s1 = 0.f, q1 = 0.f;
    #pragma unroll
    for (int nt = 0; nt < 16; nt++) {
        int col = nt * 8 + qp * 2;
        float2 e0 = (r0 < N) ? *(const float2*)(emb + (size_t)r0 * H + col) : make_float2(0.f, 0.f);
        float2 e1 = (r1 < N) ? *(const float2*)(emb + (size_t)r1 * H + col) : make_float2(0.f, 0.f);
        float z0x = 0.3f * e0.x + 0.7f * fmaxf(acc[nt].x, 0.f);
        float z0y = 0.3f * e0.y + 0.7f * fmaxf(acc[nt].y, 0.f);
        float z1x = 0.3f * e1.x + 0.7f * fmaxf(acc[nt].z, 0.f);
        float z1y = 0.3f * e1.y + 0.7f * fmaxf(acc[nt].w, 0.f);
        acc[nt] = make_float4(z0x, z0y, z1x, z1y);
        s0 += z0x + z0y; q0 += z0x * z0x + z0y * z0y;
        s1 += z1x + z1y; q1 += z1x * z1x + z1y * z1y;
    }
    #pragma unroll
    for (int off = 1; off < 4; off <<= 1) {
        s0 += __shfl_xor_sync(0xffffffffu, s0, off);
        q0 += __shfl_xor_sync(0xffffffffu, q0, off);
        s1 += __shfl_xor_sync(0xffffffffu, s1, off);
        q1 += __shfl_xor_sync(0xffffffffu, q1, off);
    }
    float m0 = s0 * (1.f / 128.f), m1 = s1 * (1.f / 128.f);
    float i0 = rsqrtf(q0 * (1.f / 128.f) - m0 * m0 + 1e-5f);
    float i1 = rsqrtf(q1 * (1.f / 128.f) - m1 * m1 + 1e-5f);
    #pragma unroll
    for (int nt = 0; nt < 16; nt++) {
        int col = nt * 8 + qp * 2;
        float2 g2 = *(const float2*)(norm_g + col);
        float2 b2 = *(const float2*)(norm_b + col);
        if (r0 < N) {
            float2 e0 = *(const float2*)(emb + (size_t)r0 * H + col);
            float vx = (acc[nt].x - m0) * i0 * g2.x + b2.x + e0.x;
            float vy = (acc[nt].y - m0) * i0 * g2.y + b2.y + e0.y;
            *(__half2*)(outh + (size_t)r0 * H + col) = __floats2half2_rn(vx, vy);
        }
        if (r1 < N) {
            float2 e1 = *(const float2*)(emb + (size_t)r1 * H + col);
            float vx = (acc[nt].z - m1) * i1 * g2.x + b2.x + e1.x;
            float vy = (acc[nt].w - m1) * i1 * g2.y + b2.y + e1.y;
            *(__half2*)(outh + (size_t)r1 * H + col) = __floats2half2_rn(vx, vy);
        }
    }
}

// K3: logits = relu(in @ mlpW^T + mlp_b) @ clfW^T + clf_b
__global__ void __launch_bounds__(256)
tgemm_head(const float* __restrict__ in, const float* __restrict__ W,
           const float* __restrict__ mlp_b,
           const float* __restrict__ clf_W, const float* __restrict__ clf_b,
           float* __restrict__ out, int N) {
    extern __shared__ __half smh[];
    __half* Ws = smh;
    __half* inS = smh + 128 * SPITCH;
    int t = threadIdx.x, lane = t & 31, warp = t >> 5;
    int grp = lane >> 2, qp = lane & 3;
    tg_load_W(W, Ws, t);
    int row0 = blockIdx.x * 128;
    tg_load_in(in, inS, row0, N, t);
    __syncthreads();
    float4 acc[16];
    tg_compute(inS, Ws, warp, grp, qp, acc);

    int r0 = row0 + warp * 16 + grp, r1 = r0 + 8;
    float p00 = 0.f, p01 = 0.f, p10 = 0.f, p11 = 0.f;
    #pragma unroll
    for (int nt = 0; nt < 16; nt++) {
        int col = nt * 8 + qp * 2;
        float2 mb = *(const float2*)(mlp_b + col);
        float2 c0 = *(const float2*)(clf_W + col);
        float2 c1 = *(const float2*)(clf_W + H + col);
        float h0x = fmaxf(acc[nt].x + mb.x, 0.f), h0y = fmaxf(acc[nt].y + mb.y, 0.f);
        float h1x = fmaxf(acc[nt].z + mb.x, 0.f), h1y = fmaxf(acc[nt].w + mb.y, 0.f);
        p00 += h0x * c0.x + h0y * c0.y;  p01 += h0x * c1.x + h0y * c1.y;
        p10 += h1x * c0.x + h1y * c0.y;  p11 += h1x * c1.x + h1y * c1.y;
    }
    #pragma unroll
    for (int off = 1; off < 4; off <<= 1) {
        p00 += __shfl_xor_sync(0xffffffffu, p00, off);
        p01 += __shfl_xor_sync(0xffffffffu, p01, off);
        p10 += __shfl_xor_sync(0xffffffffu, p10, off);
        p11 += __shfl_xor_sync(0xffffffffu, p11, off);
    }
    if (qp == 0) {
        float cb0 = clf_b[0], cb1 = clf_b[1];
        if (r0 < N) { out[(size_t)r0 * 2] = p00 + cb0; out[(size_t)r0 * 2 + 1] = p01 + cb1; }
        if (r1 < N) { out[(size_t)r1 * 2] = p10 + cb0; out[(size_t)r1 * 2 + 1] = p11 + cb1; }
    }
}

// ---------------------------------------------------------------------------
extern "C" void kernel_launch(void* const* d_in, const int* in_sizes, int n_in,
                              void* d_out, int out_size) {
    const int*   A_row  = (const int*)d_in[0];
    const int*   A_col  = (const int*)d_in[1];
    const float* A_val  = (const float*)d_in[2];
    const int*   X_row  = (const int*)d_in[3];
    const int*   X_col  = (const int*)d_in[4];
    const float* X_val  = (const float*)d_in[5];
    const float* emb_W  = (const float*)d_in[6];
    const float* lin1_W = (const float*)d_in[7];
    const float* lin2_W = (const float*)d_in[8];
    const float* norm_g = (const float*)d_in[9];
    const float* norm_b = (const float*)d_in[10];
    const float* mlp_W  = (const float*)d_in[11];
    const float* mlp_b  = (const float*)d_in[12];
    const float* clf_W  = (const float*)d_in[13];
    const float* clf_b  = (const float*)d_in[14];
    float* out = (float*)d_out;

    int E     = in_sizes[0];
    int NNZ   = in_sizes[3];
    int V     = in_sizes[6] / H;
    int NDOCS = out_size / 2;

    cudaFuncSetAttribute(tgemm_relu, cudaFuncAttributeMaxDynamicSharedMemorySize, TG_SMEM);
    cudaFuncSetAttribute(tgemm_ln,   cudaFuncAttributeMaxDynamicSharedMemorySize, TG_SMEM);
    cudaFuncSetAttribute(tgemm_head, cudaFuncAttributeMaxDynamicSharedMemorySize, TG_SMEM);

    float  *F;
    __half *Dh;
    int *cnt, *ptr, *cur, *bsum;
    int2 *edges;
    cudaGetSymbolAddress((void**)&F, g_F);
    cudaGetSymbolAddress((void**)&Dh, g_Dh);
    cudaGetSymbolAddress((void**)&cnt, g_cnt);
    cudaGetSymbolAddress((void**)&ptr, g_ptr);
    cudaGetSymbolAddress((void**)&cur, g_cur);
    cudaGetSymbolAddress((void**)&bsum, g_bsum);
    cudaGetSymbolAddress((void**)&edges, g_edges);

    int n       = V + NDOCS + 1;          // combined counters + sentinel
    int sblocks = (n + 1023) / 1024;
    int nA4     = (E + 3) / 4;
    int nX4     = (NNZ + 3) / 4;
    int eth     = nA4 + nX4;

    int spmmA_grid = (V + 7) / 8;
    int spmmX_grid = (NDOCS + 7) / 8;
    int tgV_grid   = (V + 127) / 128;
    int tgD_grid   = (NDOCS + 127) / 128;

    // Merged CSR build for A and X (5 launches total)
    zero_int_kernel<<<(n + 255) / 256, 256>>>(cnt, n);
    hist_merged_kernel<<<(eth + 255) / 256, 256>>>(A_row, E, X_row, NNZ, cnt, V);
    scan_local_kernel<<<sblocks, 1024>>>(cnt, ptr, bsum, n);
    scan_add_kernel<<<sblocks, 1024>>>(ptr, cur, bsum, n, sblocks);
    scatter_merged_kernel<<<(eth + 255) / 256, 256>>>(A_row, A_col, A_val, E,
                                                      X_row, X_col, X_val, NNZ,
                                                      cur, edges, V);
    // emb -> fp16 gather operand
    f2h_kernel<<<(V * 32 + 255) / 256, 256>>>(emb_W, Dh, V * 32);
    // 1) F = A @ Dh
    spmm_h_kernel<<<spmmA_grid, 256>>>(ptr, edges, Dh, F, V);
    // 2) Dh = f16(relu(F @ lin1^T))      [split-fp16 tensor GEMM, fp32-accurate]
    tgemm_relu<<<tgV_grid, 256, TG_SMEM>>>(F, lin1_W, Dh, V);
    // 3) F = A @ Dh
    spmm_h_kernel<<<spmmA_grid, 256>>>(ptr, edges, Dh, F, V);
    // 4) Dh = f16( layernorm(0.3*emb + 0.7*relu(F @ lin2^T)) + emb )
    tgemm_ln<<<tgV_grid, 256, TG_SMEM>>>(F, lin2_W, emb_W, norm_g, norm_b, Dh, V);
    // 5) F = X @ Dh   (Dh carries +emb, folding both X-spmms; ptr+V = X rows)
    spmm_h_kernel<<<spmmX_grid, 256>>>(ptr + V, edges, Dh, F, NDOCS);
    // 6) logits
    tgemm_head<<<tgD_grid, 256, TG_SMEM>>>(F, mlp_W, mlp_b, clf_W, clf_b, out, NDOCS);
}